// round 6
// baseline (speedup 1.0000x reference)
#include <cuda_runtime.h>

#define SEQ   512
#define DIM   512
#define HEADS 8
#define DH    64
#define DR    16
#define HD    128

// ---------------- device scratch ----------------
__device__ float g_xn  [SEQ*DIM];
__device__ float g_qkv [SEQ*3*DIM];        // q1|k1|v1
__device__ float g_aq  [SEQ*HD];
__device__ float g_ak  [SEQ*HD];
__device__ float g_av  [SEQ*HD];
__device__ float g_dots[HEADS*SEQ*SEQ];    // dots2 lower-tri, then attn in place
__device__ float g_uv  [(size_t)SEQ*SEQ*HD];
__device__ float g_uk  [(size_t)4096*8192]; // per-block accK spill (L2-hot)
__device__ float g_out1[SEQ*DIM];
__device__ float g_out2[SEQ*HD];
__device__ float g_tmp [SEQ*DIM];

// ---------------- helpers ----------------
__device__ __forceinline__ float to_tf32(float x) {
    unsigned u;
    asm("cvt.rna.tf32.f32 %0, %1;" : "=r"(u) : "f"(x));
    return __uint_as_float(u);
}
__device__ __forceinline__ void mma_tf32(float c[4], unsigned a0, unsigned a1, unsigned a2, unsigned a3,
                                         unsigned b0, unsigned b1) {
    asm volatile("mma.sync.aligned.m16n8k8.row.col.f32.tf32.tf32.f32 "
                 "{%0,%1,%2,%3}, {%4,%5,%6,%7}, {%8,%9}, {%0,%1,%2,%3};"
                 : "+f"(c[0]), "+f"(c[1]), "+f"(c[2]), "+f"(c[3])
                 : "r"(a0), "r"(a1), "r"(a2), "r"(a3), "r"(b0), "r"(b1));
}

// ---------------- layernorm ----------------
__global__ void __launch_bounds__(256) ln_kernel(const float* __restrict__ x,
                                                 const float* __restrict__ w,
                                                 const float* __restrict__ b) {
    int row = blockIdx.x;
    int tid = threadIdx.x;
    const float* xr = x + row*DIM;
    __shared__ float red[20];
    float v0 = xr[tid], v1 = xr[tid+256];
    float s = v0 + v1;
    #pragma unroll
    for (int o=16;o;o>>=1) s += __shfl_xor_sync(0xffffffffu, s, o);
    if ((tid&31)==0) red[tid>>5] = s;
    __syncthreads();
    if (tid < 8) {
        s = red[tid];
        #pragma unroll
        for (int o=4;o;o>>=1) s += __shfl_xor_sync(0xffu, s, o);
        if (tid==0) red[16] = s;
    }
    __syncthreads();
    float mu = red[16] * (1.0f/DIM);
    float d0 = v0-mu, d1 = v1-mu;
    float q = d0*d0 + d1*d1;
    #pragma unroll
    for (int o=16;o;o>>=1) q += __shfl_xor_sync(0xffffffffu, q, o);
    if ((tid&31)==0) red[8 + (tid>>5)] = q;
    __syncthreads();
    if (tid < 8) {
        q = red[8+tid];
        #pragma unroll
        for (int o=4;o;o>>=1) q += __shfl_xor_sync(0xffu, q, o);
        if (tid==0) red[17] = q;
    }
    __syncthreads();
    float inv = rsqrtf(red[17]*(1.0f/DIM) + 1e-5f);
    g_xn[row*DIM + tid]     = d0*inv*w[tid]     + b[tid];
    g_xn[row*DIM + tid+256] = d1*inv*w[tid+256] + b[tid+256];
}

// ---------------- generic tf32 MMA GEMM: C[M,N] = A[M,K] @ B[K,N], tile 64x64 ----------------
struct SmemGemm { float sA[64][36]; float sB[32][68]; };

template<int EPI>
__device__ __forceinline__ void gemm_body(const float* __restrict__ A, const float* __restrict__ B,
                                          float* __restrict__ C, int N, int K,
                                          const float* __restrict__ add,
                                          SmemGemm& sm, int m0, int n0) {
    int tid = threadIdx.x;
    int warp = tid>>5, lane = tid&31;
    int qrow = lane>>2, qcol = lane&3;
    int m_base = (warp&3)*16, n_base = (warp>>2)*32;
    float acc[4][4] = {};
    for (int kc = 0; kc < K; kc += 32) {
        __syncthreads();
        #pragma unroll
        for (int q=0;q<2;q++) {
            int idx = q*256+tid; int r = idx>>3, c4 = idx&7;
            float4 v = *(const float4*)(A + (m0+r)*K + kc + c4*4);
            sm.sA[r][c4*4+0]=to_tf32(v.x); sm.sA[r][c4*4+1]=to_tf32(v.y);
            sm.sA[r][c4*4+2]=to_tf32(v.z); sm.sA[r][c4*4+3]=to_tf32(v.w);
        }
        #pragma unroll
        for (int q=0;q<2;q++) {
            int idx = q*256+tid; int r = idx>>4, c4 = idx&15;
            float4 v = *(const float4*)(B + (kc+r)*N + n0 + c4*4);
            sm.sB[r][c4*4+0]=to_tf32(v.x); sm.sB[r][c4*4+1]=to_tf32(v.y);
            sm.sB[r][c4*4+2]=to_tf32(v.z); sm.sB[r][c4*4+3]=to_tf32(v.w);
        }
        __syncthreads();
        #pragma unroll
        for (int ks=0; ks<4; ks++) {
            int k0 = ks*8;
            unsigned a0 = __float_as_uint(sm.sA[m_base+qrow  ][k0+qcol  ]);
            unsigned a1 = __float_as_uint(sm.sA[m_base+qrow+8][k0+qcol  ]);
            unsigned a2 = __float_as_uint(sm.sA[m_base+qrow  ][k0+qcol+4]);
            unsigned a3 = __float_as_uint(sm.sA[m_base+qrow+8][k0+qcol+4]);
            #pragma unroll
            for (int nf=0; nf<4; nf++) {
                unsigned b0 = __float_as_uint(sm.sB[k0+qcol  ][n_base+nf*8+qrow]);
                unsigned b1 = __float_as_uint(sm.sB[k0+qcol+4][n_base+nf*8+qrow]);
                mma_tf32(acc[nf], a0,a1,a2,a3, b0,b1);
            }
        }
    }
    #pragma unroll
    for (int nf=0; nf<4; nf++) {
        int col = n0 + n_base + nf*8 + 2*qcol;
        int r0 = m0 + m_base + qrow, r1 = r0 + 8;
        float2 v0 = make_float2(acc[nf][0], acc[nf][1]);
        float2 v1 = make_float2(acc[nf][2], acc[nf][3]);
        if (EPI==1) {
            const float* p0 = add + (size_t)r0*N + col;
            const float* p1 = add + (size_t)r1*N + col;
            v0.x = (v0.x + p0[0])*0.5f; v0.y = (v0.y + p0[1])*0.5f;
            v1.x = (v1.x + p1[0])*0.5f; v1.y = (v1.y + p1[1])*0.5f;
        } else if (EPI==2) {
            v0.x += add[col]; v0.y += add[col+1];
            v1.x += add[col]; v1.y += add[col+1];
        }
        *(float2*)(C + (size_t)r0*N + col) = v0;
        *(float2*)(C + (size_t)r1*N + col) = v1;
    }
}

template<int EPI>
__global__ void __launch_bounds__(256) mma_gemm(const float* __restrict__ A, const float* __restrict__ B,
                                                float* __restrict__ C, int N, int K,
                                                const float* __restrict__ add) {
    __shared__ SmemGemm sm;
    gemm_body<EPI>(A, B, C, N, K, add, sm, blockIdx.y*64, blockIdx.x*64);
}

// fused q1/k1/v1 projections (z selects weight/output)
__global__ void __launch_bounds__(256) mma_gemm3(const float* __restrict__ A,
                                                 const float* __restrict__ B0, const float* __restrict__ B1,
                                                 const float* __restrict__ B2,
                                                 float* C0, float* C1, float* C2, int N, int K) {
    __shared__ SmemGemm sm;
    const float* B = blockIdx.z==0 ? B0 : (blockIdx.z==1 ? B1 : B2);
    float* C       = blockIdx.z==0 ? C0 : (blockIdx.z==1 ? C1 : C2);
    gemm_body<0>(A, B, C, N, K, nullptr, sm, blockIdx.y*64, blockIdx.x*64);
}

// ---------------- per-diagonal rel-projection via tf32 MMA ----------------
// Block: 128 threads = 4 warps; tile m64 x n128 x k128; warp tile m32 x n64.
// Order K -> Q -> V with ONE live accumulator; accK spilled to g_uk (same-thread
// readback, L2-hot) so regs stay low enough for 3 blocks/SM.
__global__ void __launch_bounds__(128,3) diag_mma(const float* __restrict__ Pq,
                                                  const float* __restrict__ Pk,
                                                  const float* __restrict__ Pv) {
    int d  = blockIdx.y;
    int nj = SEQ - d;
    int j0 = blockIdx.x * 64;
    if (j0 >= nj) return;
    int nvalid = min(64, nj - j0);

    __shared__ float sA[64][132];
    __shared__ float sP[16][132];
    int tid = threadIdx.x, warp = tid>>5, lane = tid&31;
    int qrow = lane>>2, qcol = lane&3;
    int m_base = (warp&1)*32, n_base = (warp>>1)*64;

    float* ukbase = g_uk + ((size_t)(blockIdx.y*8 + blockIdx.x))*8192 + tid*64;

    auto loadA = [&](const float* __restrict__ Ab, int rowbase) {
        #pragma unroll
        for (int q=0;q<16;q++) {
            int idx = q*128+tid; int r = idx>>5, c4 = idx&31;
            float4 v = make_float4(0.f,0.f,0.f,0.f);
            if (r < nvalid) v = *(const float4*)(Ab + (rowbase+r)*HD + c4*4);
            v.x=to_tf32(v.x); v.y=to_tf32(v.y); v.z=to_tf32(v.z); v.w=to_tf32(v.w);
            *(float4*)&sA[r][c4*4] = v;
        }
    };

    // acc layout: acc[mf*8+nf][4], mf in {0,1} (rows m_base+mf*16), nf in {0..7}
    auto gemm = [&](const float* __restrict__ P, float acc[16][4]) {
        int pr = tid>>5, pc4 = tid&31;           // each warp fills rows pr, pr+4, pr+8, pr+12
        const float* Pt = P + pr*HD + pc4*4;
        float4 pre[4];
        #pragma unroll
        for (int q=0;q<4;q++) pre[q] = *(const float4*)(Pt + q*4*HD);
        for (int kc=0; kc<128; kc+=16) {
            __syncthreads();
            #pragma unroll
            for (int q=0;q<4;q++) {
                float4 v = pre[q];
                v.x=to_tf32(v.x); v.y=to_tf32(v.y); v.z=to_tf32(v.z); v.w=to_tf32(v.w);
                *(float4*)&sP[pr + q*4][pc4*4] = v;
            }
            __syncthreads();
            if (kc + 16 < 128) {
                #pragma unroll
                for (int q=0;q<4;q++) pre[q] = *(const float4*)(Pt + (kc+16)*HD + q*4*HD);
            }
            #pragma unroll
            for (int ks=0; ks<2; ks++) {
                int k0 = kc + ks*8;
                unsigned a[2][4];
                #pragma unroll
                for (int mf=0; mf<2; mf++) {
                    int mr = m_base + mf*16 + qrow;
                    a[mf][0] = __float_as_uint(sA[mr  ][k0+qcol  ]);
                    a[mf][1] = __float_as_uint(sA[mr+8][k0+qcol  ]);
                    a[mf][2] = __float_as_uint(sA[mr  ][k0+qcol+4]);
                    a[mf][3] = __float_as_uint(sA[mr+8][k0+qcol+4]);
                }
                #pragma unroll
                for (int nf=0; nf<8; nf++) {
                    unsigned b0 = __float_as_uint(sP[ks*8+qcol  ][n_base+nf*8+qrow]);
                    unsigned b1 = __float_as_uint(sP[ks*8+qcol+4][n_base+nf*8+qrow]);
                    mma_tf32(acc[nf],   a[0][0],a[0][1],a[0][2],a[0][3], b0,b1);
                    mma_tf32(acc[8+nf], a[1][0],a[1][1],a[1][2],a[1][3], b0,b1);
                }
            }
        }
    };

    float acc[16][4];

    // ---- K: rows j0.. with Pk[d] ----
    #pragma unroll
    for (int f=0;f<16;f++) { acc[f][0]=0.f; acc[f][1]=0.f; acc[f][2]=0.f; acc[f][3]=0.f; }
    loadA(g_ak, j0);
    gemm(Pk + (size_t)d*HD*HD, acc);
    // spill accK fragments (same thread reads them back later)
    #pragma unroll
    for (int f=0;f<16;f++) *(float4*)(ukbase + f*4) = *(float4*)acc[f];

    // ---- Q: rows j0+d.. with Pq[511-d] ----
    __syncthreads();
    #pragma unroll
    for (int f=0;f<16;f++) { acc[f][0]=0.f; acc[f][1]=0.f; acc[f][2]=0.f; acc[f][3]=0.f; }
    loadA(g_aq, j0 + d);
    gemm(Pq + (size_t)(SEQ-1-d)*HD*HD, acc);

    // dots2[h, j+d, j]: per-head (16 cols) dot of Uq (acc) and Uk (g_uk readback)
    #pragma unroll
    for (int mf=0; mf<2; mf++) {
        #pragma unroll
        for (int hh=0; hh<4; hh++) {
            int f0 = mf*8 + 2*hh, f1 = f0 + 1;
            float4 k0v = *(const float4*)(ukbase + f0*4);
            float4 k1v = *(const float4*)(ukbase + f1*4);
            float p0 = acc[f0][0]*k0v.x + acc[f0][1]*k0v.y
                     + acc[f1][0]*k1v.x + acc[f1][1]*k1v.y;
            float p1 = acc[f0][2]*k0v.z + acc[f0][3]*k0v.w
                     + acc[f1][2]*k1v.z + acc[f1][3]*k1v.w;
            p0 += __shfl_xor_sync(0xffffffffu, p0, 1);
            p0 += __shfl_xor_sync(0xffffffffu, p0, 2);
            p1 += __shfl_xor_sync(0xffffffffu, p1, 1);
            p1 += __shfl_xor_sync(0xffffffffu, p1, 2);
            if (qcol == 0) {
                int h = (n_base>>4) + hh;
                int r0 = m_base + mf*16 + qrow;
                if (r0 < nvalid) { int j = j0 + r0; g_dots[(size_t)h*SEQ*SEQ + (size_t)(j+d)*SEQ + j] = p0; }
                int r1 = r0 + 8;
                if (r1 < nvalid) { int j = j0 + r1; g_dots[(size_t)h*SEQ*SEQ + (size_t)(j+d)*SEQ + j] = p1; }
            }
        }
    }

    // ---- V: rows j0.. with Pv[d] -> g_uv[d][j][:] ----
    __syncthreads();
    #pragma unroll
    for (int f=0;f<16;f++) { acc[f][0]=0.f; acc[f][1]=0.f; acc[f][2]=0.f; acc[f][3]=0.f; }
    loadA(g_av, j0);
    gemm(Pv + (size_t)d*HD*HD, acc);
    #pragma unroll
    for (int mf=0; mf<2; mf++) {
        #pragma unroll
        for (int nf=0; nf<8; nf++) {
            int col = n_base + nf*8 + 2*qcol;
            int r0 = m_base + mf*16 + qrow;
            if (r0 < nvalid)
                *(float2*)(g_uv + ((size_t)d*SEQ + j0 + r0)*HD + col) = make_float2(acc[mf*8+nf][0], acc[mf*8+nf][1]);
            int r1 = r0 + 8;
            if (r1 < nvalid)
                *(float2*)(g_uv + ((size_t)d*SEQ + j0 + r1)*HD + col) = make_float2(acc[mf*8+nf][2], acc[mf*8+nf][3]);
        }
    }
}

// ---------------- dots1 + combine + causal softmax ----------------
__global__ void __launch_bounds__(256) attn_kernel() {
    int h  = blockIdx.y;
    int i0 = blockIdx.x * 16;
    __shared__ float sQ[16][68];
    __shared__ float sK[32][68];
    __shared__ float sD[16][512];
    int tid = threadIdx.x;
    {   int r = tid>>4, c4 = tid&15;
        *(float4*)&sQ[r][c4*4] = *(const float4*)(g_qkv + (i0+r)*1536 + h*64 + c4*4); }
    int r2 = tid>>4, jj = tid&15;
    for (int jc = 0; jc < 512; jc += 32) {
        __syncthreads();
        #pragma unroll
        for (int q=0; q<2; q++) {
            int idx = q*256 + tid; int r = idx>>4, c4 = idx&15;
            *(float4*)&sK[r][c4*4] = *(const float4*)(g_qkv + (jc+r)*1536 + 512 + h*64 + c4*4);
        }
        __syncthreads();
        float a0 = 0.f, a1 = 0.f;
        #pragma unroll
        for (int c=0; c<64; c++) {
            float qv = sQ[r2][c];
            a0 += qv * sK[jj][c];
            a1 += qv * sK[jj+16][c];
        }
        sD[r2][jc+jj]    = a0;
        sD[r2][jc+jj+16] = a1;
    }
    __syncthreads();
    int w = tid>>5, lane = tid&31;
    for (int rr = 2*w; rr < 2*w+2; rr++) {
        int i = i0 + rr;
        float vals[16];
        float m = -1e30f;
        #pragma unroll
        for (int t=0; t<16; t++) {
            int j = lane + t*32;
            float dv = -1e30f;
            if (j <= i)
                dv = 0.0625f * (sD[rr][j] + g_dots[(size_t)h*SEQ*SEQ + (size_t)i*SEQ + j]);
            vals[t] = dv;
            m = fmaxf(m, dv);
        }
        #pragma unroll
        for (int o=16;o;o>>=1) m = fmaxf(m, __shfl_xor_sync(0xffffffffu, m, o));
        float s = 0.f;
        #pragma unroll
        for (int t=0; t<16; t++) {
            float e = (vals[t] > -1e29f) ? __expf(vals[t]-m) : 0.f;
            vals[t] = e; s += e;
        }
        #pragma unroll
        for (int o=16;o;o>>=1) s += __shfl_xor_sync(0xffffffffu, s, o);
        float inv = 1.f / s;
        #pragma unroll
        for (int t=0; t<16; t++) {
            int j = lane + t*32;
            g_dots[(size_t)h*SEQ*SEQ + (size_t)i*SEQ + j] = vals[t]*inv;
        }
    }
}

// ---------------- out1 = attn @ v1 ----------------
__global__ void __launch_bounds__(256) out1_kernel() {
    int h = blockIdx.y, i0 = blockIdx.x*32;
    __shared__ float sAt[32][36];
    __shared__ float sV[32][68];
    int tid = threadIdx.x, ty = tid>>4, tx = tid&15;
    float acc[2][4] = {};
    for (int jc = 0; jc < 512; jc += 32) {
        __syncthreads();
        {   int r = tid>>3, c4 = tid&7;
            *(float4*)&sAt[r][c4*4] = *(const float4*)(g_dots + (size_t)h*SEQ*SEQ + (size_t)(i0+r)*512 + jc + c4*4); }
        #pragma unroll
        for (int q=0; q<2; q++) {
            int idx = q*256 + tid; int r = idx>>4, c4 = idx&15;
            *(float4*)&sV[r][c4*4] = *(const float4*)(g_qkv + (jc+r)*1536 + 1024 + h*64 + c4*4);
        }
        __syncthreads();
        #pragma unroll
        for (int k=0; k<32; k++) {
            float a0 = sAt[ty][k], a1 = sAt[ty+16][k];
            float4 v4 = *(float4*)&sV[k][tx*4];
            acc[0][0]+=a0*v4.x; acc[0][1]+=a0*v4.y; acc[0][2]+=a0*v4.z; acc[0][3]+=a0*v4.w;
            acc[1][0]+=a1*v4.x; acc[1][1]+=a1*v4.y; acc[1][2]+=a1*v4.z; acc[1][3]+=a1*v4.w;
        }
    }
    *(float4*)(g_out1 + (i0+ty)*512    + h*64 + tx*4) = make_float4(acc[0][0],acc[0][1],acc[0][2],acc[0][3]);
    *(float4*)(g_out1 + (i0+ty+16)*512 + h*64 + tx*4) = make_float4(acc[1][0],acc[1][1],acc[1][2],acc[1][3]);
}

// ---------------- out2[i,c] = sum_{j<=i} attn[h(c),i,j] * Uv[i-j][j][c] ----------------
__global__ void __launch_bounds__(512) out2_kernel() {
    int i = blockIdx.x;
    int tid = threadIdx.x;
    int c = tid & 127;
    int part = tid >> 7;
    int h = c >> 4;
    const float* arow = g_dots + (size_t)h*SEQ*SEQ + (size_t)i*SEQ;
    int len = i + 1;
    int chunk = (len + 3) >> 2;
    int jb = part*chunk, je = min(len, jb + chunk);
    float a0=0.f, a1=0.f, a2=0.f, a3=0.f;
    int j = jb;
    for (; j+4 <= je; j += 4) {
        a0 += arow[j]   * g_uv[((size_t)(i-j  )*SEQ + j  )*HD + c];
        a1 += arow[j+1] * g_uv[((size_t)(i-j-1)*SEQ + j+1)*HD + c];
        a2 += arow[j+2] * g_uv[((size_t)(i-j-2)*SEQ + j+2)*HD + c];
        a3 += arow[j+3] * g_uv[((size_t)(i-j-3)*SEQ + j+3)*HD + c];
    }
    for (; j < je; j++)
        a0 += arow[j] * g_uv[((size_t)(i-j)*SEQ + j)*HD + c];
    __shared__ float red[512];
    red[tid] = (a0+a1) + (a2+a3);
    __syncthreads();
    if (part == 0)
        g_out2[i*HD + c] = (red[c] + red[c+128]) + (red[c+256] + red[c+384]);
}

// ---------------- launch ----------------
extern "C" void kernel_launch(void* const* d_in, const int* in_sizes, int n_in,
                              void* d_out, int out_size) {
    const float* x     = (const float*)d_in[0];
    const float* ln_w  = (const float*)d_in[1];
    const float* ln_b  = (const float*)d_in[2];
    const float* w_qkv = (const float*)d_in[3];
    const float* w_q1  = (const float*)d_in[4];
    const float* p_q2  = (const float*)d_in[5];
    const float* w_k1  = (const float*)d_in[6];
    const float* p_k2  = (const float*)d_in[7];
    const float* w_v1  = (const float*)d_in[8];
    const float* p_v2  = (const float*)d_in[9];
    const float* w_v3  = (const float*)d_in[10];
    const float* w_out = (const float*)d_in[11];
    const float* b_out = (const float*)d_in[12];
    float* out = (float*)d_out;

    float *p_xn, *p_qkvb, *p_aq, *p_ak, *p_av, *p_out1b, *p_out2b, *p_tmpb;
    cudaGetSymbolAddress((void**)&p_xn,   g_xn);
    cudaGetSymbolAddress((void**)&p_qkvb, g_qkv);
    cudaGetSymbolAddress((void**)&p_aq,   g_aq);
    cudaGetSymbolAddress((void**)&p_ak,   g_ak);
    cudaGetSymbolAddress((void**)&p_av,   g_av);
    cudaGetSymbolAddress((void**)&p_out1b,g_out1);
    cudaGetSymbolAddress((void**)&p_out2b,g_out2);
    cudaGetSymbolAddress((void**)&p_tmpb, g_tmp);

    ln_kernel<<<512, 256>>>(x, ln_w, ln_b);

    // qkv = xn @ w_qkv  (512x1536x512)
    mma_gemm<0><<<dim3(24,8), 256>>>(p_xn, w_qkv, p_qkvb, 1536, 512, nullptr);
    // aq/ak/av = xn @ {w_q1,w_k1,w_v1}  (512x128x512, fused)
    mma_gemm3<<<dim3(2,8,3), 256>>>(p_xn, w_q1, w_k1, w_v1, p_aq, p_ak, p_av, 128, 512);

    diag_mma<<<dim3(8,512), 128>>>(p_q2, p_k2, p_v2);

    attn_kernel<<<dim3(32,8), 256>>>();
    out1_kernel<<<dim3(16,8), 256>>>();
    out2_kernel<<<512, 512>>>();

    // tmp = (out1 + out2 @ w_v3) * 0.5   (512x512x128)
    mma_gemm<1><<<dim3(8,8), 256>>>(p_out2b, w_v3, p_tmpb, 512, 128, p_out1b);
    // out = tmp @ w_out + b_out          (512x512x512)
    mma_gemm<2><<<dim3(8,8), 256>>>(p_tmpb, w_out, out, 512, 512, b_out);
}

// round 7
// speedup vs baseline: 1.0662x; 1.0662x over previous
#include <cuda_runtime.h>

#define SEQ   512
#define DIM   512
#define HEADS 8
#define DH    64
#define DR    16
#define HD    128

// ---------------- device scratch ----------------
__device__ float g_xn  [SEQ*DIM];
__device__ float g_qkv [SEQ*3*DIM];        // q1|k1|v1
__device__ float g_aq  [SEQ*HD];
__device__ float g_ak  [SEQ*HD];
__device__ float g_av  [SEQ*HD];
__device__ float g_dots[HEADS*SEQ*SEQ];    // dots2 lower-tri, then attn in place
__device__ float g_uv  [(size_t)SEQ*SEQ*HD];
__device__ float g_out1[SEQ*DIM];
__device__ float g_out2[SEQ*HD];
__device__ float g_tmp [SEQ*DIM];

// ---------------- helpers ----------------
__device__ __forceinline__ float to_tf32(float x) {
    unsigned u;
    asm("cvt.rna.tf32.f32 %0, %1;" : "=r"(u) : "f"(x));
    return __uint_as_float(u);
}
__device__ __forceinline__ void mma_tf32(float c[4], unsigned a0, unsigned a1, unsigned a2, unsigned a3,
                                         unsigned b0, unsigned b1) {
    asm volatile("mma.sync.aligned.m16n8k8.row.col.f32.tf32.tf32.f32 "
                 "{%0,%1,%2,%3}, {%4,%5,%6,%7}, {%8,%9}, {%0,%1,%2,%3};"
                 : "+f"(c[0]), "+f"(c[1]), "+f"(c[2]), "+f"(c[3])
                 : "r"(a0), "r"(a1), "r"(a2), "r"(a3), "r"(b0), "r"(b1));
}

// ---------------- layernorm ----------------
__global__ void __launch_bounds__(256) ln_kernel(const float* __restrict__ x,
                                                 const float* __restrict__ w,
                                                 const float* __restrict__ b) {
    int row = blockIdx.x;
    int tid = threadIdx.x;
    const float* xr = x + row*DIM;
    __shared__ float red[20];
    float v0 = xr[tid], v1 = xr[tid+256];
    float s = v0 + v1;
    #pragma unroll
    for (int o=16;o;o>>=1) s += __shfl_xor_sync(0xffffffffu, s, o);
    if ((tid&31)==0) red[tid>>5] = s;
    __syncthreads();
    if (tid < 8) {
        s = red[tid];
        #pragma unroll
        for (int o=4;o;o>>=1) s += __shfl_xor_sync(0xffu, s, o);
        if (tid==0) red[16] = s;
    }
    __syncthreads();
    float mu = red[16] * (1.0f/DIM);
    float d0 = v0-mu, d1 = v1-mu;
    float q = d0*d0 + d1*d1;
    #pragma unroll
    for (int o=16;o;o>>=1) q += __shfl_xor_sync(0xffffffffu, q, o);
    if ((tid&31)==0) red[8 + (tid>>5)] = q;
    __syncthreads();
    if (tid < 8) {
        q = red[8+tid];
        #pragma unroll
        for (int o=4;o;o>>=1) q += __shfl_xor_sync(0xffu, q, o);
        if (tid==0) red[17] = q;
    }
    __syncthreads();
    float inv = rsqrtf(red[17]*(1.0f/DIM) + 1e-5f);
    g_xn[row*DIM + tid]     = d0*inv*w[tid]     + b[tid];
    g_xn[row*DIM + tid+256] = d1*inv*w[tid+256] + b[tid+256];
}

// ---------------- generic tf32 MMA GEMM: C[M,N] = A[M,K] @ B[K,N], tile 64x64 ----------------
struct SmemGemm { float sA[64][36]; float sB[32][68]; };

template<int EPI>
__device__ __forceinline__ void gemm_body(const float* __restrict__ A, const float* __restrict__ B,
                                          float* __restrict__ C, int N, int K,
                                          const float* __restrict__ add,
                                          SmemGemm& sm, int m0, int n0) {
    int tid = threadIdx.x;
    int warp = tid>>5, lane = tid&31;
    int qrow = lane>>2, qcol = lane&3;
    int m_base = (warp&3)*16, n_base = (warp>>2)*32;
    float acc[4][4] = {};
    for (int kc = 0; kc < K; kc += 32) {
        __syncthreads();
        #pragma unroll
        for (int q=0;q<2;q++) {
            int idx = q*256+tid; int r = idx>>3, c4 = idx&7;
            float4 v = *(const float4*)(A + (m0+r)*K + kc + c4*4);
            sm.sA[r][c4*4+0]=to_tf32(v.x); sm.sA[r][c4*4+1]=to_tf32(v.y);
            sm.sA[r][c4*4+2]=to_tf32(v.z); sm.sA[r][c4*4+3]=to_tf32(v.w);
        }
        #pragma unroll
        for (int q=0;q<2;q++) {
            int idx = q*256+tid; int r = idx>>4, c4 = idx&15;
            float4 v = *(const float4*)(B + (kc+r)*N + n0 + c4*4);
            sm.sB[r][c4*4+0]=to_tf32(v.x); sm.sB[r][c4*4+1]=to_tf32(v.y);
            sm.sB[r][c4*4+2]=to_tf32(v.z); sm.sB[r][c4*4+3]=to_tf32(v.w);
        }
        __syncthreads();
        #pragma unroll
        for (int ks=0; ks<4; ks++) {
            int k0 = ks*8;
            unsigned a0 = __float_as_uint(sm.sA[m_base+qrow  ][k0+qcol  ]);
            unsigned a1 = __float_as_uint(sm.sA[m_base+qrow+8][k0+qcol  ]);
            unsigned a2 = __float_as_uint(sm.sA[m_base+qrow  ][k0+qcol+4]);
            unsigned a3 = __float_as_uint(sm.sA[m_base+qrow+8][k0+qcol+4]);
            #pragma unroll
            for (int nf=0; nf<4; nf++) {
                unsigned b0 = __float_as_uint(sm.sB[k0+qcol  ][n_base+nf*8+qrow]);
                unsigned b1 = __float_as_uint(sm.sB[k0+qcol+4][n_base+nf*8+qrow]);
                mma_tf32(acc[nf], a0,a1,a2,a3, b0,b1);
            }
        }
    }
    #pragma unroll
    for (int nf=0; nf<4; nf++) {
        int col = n0 + n_base + nf*8 + 2*qcol;
        int r0 = m0 + m_base + qrow, r1 = r0 + 8;
        float2 v0 = make_float2(acc[nf][0], acc[nf][1]);
        float2 v1 = make_float2(acc[nf][2], acc[nf][3]);
        if (EPI==1) {
            const float* p0 = add + (size_t)r0*N + col;
            const float* p1 = add + (size_t)r1*N + col;
            v0.x = (v0.x + p0[0])*0.5f; v0.y = (v0.y + p0[1])*0.5f;
            v1.x = (v1.x + p1[0])*0.5f; v1.y = (v1.y + p1[1])*0.5f;
        } else if (EPI==2) {
            v0.x += add[col]; v0.y += add[col+1];
            v1.x += add[col]; v1.y += add[col+1];
        }
        *(float2*)(C + (size_t)r0*N + col) = v0;
        *(float2*)(C + (size_t)r1*N + col) = v1;
    }
}

template<int EPI>
__global__ void __launch_bounds__(256) mma_gemm(const float* __restrict__ A, const float* __restrict__ B,
                                                float* __restrict__ C, int N, int K,
                                                const float* __restrict__ add) {
    __shared__ SmemGemm sm;
    gemm_body<EPI>(A, B, C, N, K, add, sm, blockIdx.y*64, blockIdx.x*64);
}

// fused q1/k1/v1 projections (z selects weight/output)
__global__ void __launch_bounds__(256) mma_gemm3(const float* __restrict__ A,
                                                 const float* __restrict__ B0, const float* __restrict__ B1,
                                                 const float* __restrict__ B2,
                                                 float* C0, float* C1, float* C2, int N, int K) {
    __shared__ SmemGemm sm;
    const float* B = blockIdx.z==0 ? B0 : (blockIdx.z==1 ? B1 : B2);
    float* C       = blockIdx.z==0 ? C0 : (blockIdx.z==1 ? C1 : C2);
    gemm_body<0>(A, B, C, N, K, nullptr, sm, blockIdx.y*64, blockIdx.x*64);
}

// ---------------- per-diagonal rel-projection via tf32 MMA ----------------
// Block: 128 threads = 4 warps; tile m64 x k128.
// Q/K done per 64-col half (heads 0-3, then 4-7): accQ+accK = 64 regs live.
// V done full-width (single 64-reg acc). No spills, no extra global traffic.
__global__ void __launch_bounds__(128,4) diag_mma(const float* __restrict__ Pq,
                                                  const float* __restrict__ Pk,
                                                  const float* __restrict__ Pv) {
    int d  = blockIdx.y;
    int nj = SEQ - d;
    int j0 = blockIdx.x * 64;
    if (j0 >= nj) return;
    int nvalid = min(64, nj - j0);

    __shared__ float sA[64][132];
    __shared__ float sP[16][132];
    int tid = threadIdx.x, warp = tid>>5, lane = tid&31;
    int qrow = lane>>2, qcol = lane&3;

    // guard previous MMA reads of sA, then refill
    auto loadA = [&](const float* __restrict__ Ab, int rowbase) {
        __syncthreads();
        #pragma unroll
        for (int q=0;q<16;q++) {
            int idx = q*128+tid; int r = idx>>5, c4 = idx&31;
            float4 v = make_float4(0.f,0.f,0.f,0.f);
            if (r < nvalid) v = *(const float4*)(Ab + (rowbase+r)*HD + c4*4);
            v.x=to_tf32(v.x); v.y=to_tf32(v.y); v.z=to_tf32(v.z); v.w=to_tf32(v.w);
            *(float4*)&sA[r][c4*4] = v;
        }
    };

    // ---- half-width gemm: B cols [c0, c0+64), warp tile m32 x n32 ----
    // acc[mf*4+nf][4], mf in {0,1}, nf in {0..3}
    auto gemm_h = [&](const float* __restrict__ P, int c0, float acc[8][4]) {
        int m_base = (warp&1)*32, n_base = (warp>>1)*32;
        int pr = tid>>4, pc4 = tid&15;                 // rows pr, pr+8 ; 16 float4-cols
        const float* Pt = P + pr*HD + c0 + pc4*4;
        float4 pre[2];
        #pragma unroll
        for (int q=0;q<2;q++) pre[q] = *(const float4*)(Pt + q*8*HD);
        for (int kc=0; kc<128; kc+=16) {
            __syncthreads();
            #pragma unroll
            for (int q=0;q<2;q++) {
                float4 v = pre[q];
                v.x=to_tf32(v.x); v.y=to_tf32(v.y); v.z=to_tf32(v.z); v.w=to_tf32(v.w);
                *(float4*)&sP[pr + q*8][pc4*4] = v;
            }
            __syncthreads();
            if (kc + 16 < 128) {
                #pragma unroll
                for (int q=0;q<2;q++) pre[q] = *(const float4*)(Pt + (kc+16+q*8)*HD);
            }
            #pragma unroll
            for (int ks=0; ks<2; ks++) {
                int k0 = kc + ks*8;
                unsigned a[2][4];
                #pragma unroll
                for (int mf=0; mf<2; mf++) {
                    int mr = m_base + mf*16 + qrow;
                    a[mf][0] = __float_as_uint(sA[mr  ][k0+qcol  ]);
                    a[mf][1] = __float_as_uint(sA[mr+8][k0+qcol  ]);
                    a[mf][2] = __float_as_uint(sA[mr  ][k0+qcol+4]);
                    a[mf][3] = __float_as_uint(sA[mr+8][k0+qcol+4]);
                }
                #pragma unroll
                for (int nf=0; nf<4; nf++) {
                    unsigned b0 = __float_as_uint(sP[ks*8+qcol  ][n_base+nf*8+qrow]);
                    unsigned b1 = __float_as_uint(sP[ks*8+qcol+4][n_base+nf*8+qrow]);
                    mma_tf32(acc[nf],   a[0][0],a[0][1],a[0][2],a[0][3], b0,b1);
                    mma_tf32(acc[4+nf], a[1][0],a[1][1],a[1][2],a[1][3], b0,b1);
                }
            }
        }
    };

    // dots2 epilogue for one half: per-head 16-col dots of accQ,accK
    auto dots2_h = [&](float accQ[8][4], float accK[8][4], int half) {
        int m_base = (warp&1)*32;
        #pragma unroll
        for (int mf=0; mf<2; mf++) {
            #pragma unroll
            for (int hh=0; hh<2; hh++) {
                int f0 = mf*4 + 2*hh, f1 = f0 + 1;
                float p0 = accQ[f0][0]*accK[f0][0] + accQ[f0][1]*accK[f0][1]
                         + accQ[f1][0]*accK[f1][0] + accQ[f1][1]*accK[f1][1];
                float p1 = accQ[f0][2]*accK[f0][2] + accQ[f0][3]*accK[f0][3]
                         + accQ[f1][2]*accK[f1][2] + accQ[f1][3]*accK[f1][3];
                p0 += __shfl_xor_sync(0xffffffffu, p0, 1);
                p0 += __shfl_xor_sync(0xffffffffu, p0, 2);
                p1 += __shfl_xor_sync(0xffffffffu, p1, 1);
                p1 += __shfl_xor_sync(0xffffffffu, p1, 2);
                if (qcol == 0) {
                    int h = half*4 + ((warp>>1)<<1) + hh;
                    int r0 = m_base + mf*16 + qrow;
                    if (r0 < nvalid) { int j = j0 + r0; g_dots[(size_t)h*SEQ*SEQ + (size_t)(j+d)*SEQ + j] = p0; }
                    int r1 = r0 + 8;
                    if (r1 < nvalid) { int j = j0 + r1; g_dots[(size_t)h*SEQ*SEQ + (size_t)(j+d)*SEQ + j] = p1; }
                }
            }
        }
    };

    const float* Pk_d = Pk + (size_t)d*HD*HD;
    const float* Pq_d = Pq + (size_t)(SEQ-1-d)*HD*HD;

    float accK[8][4], accQ[8][4];

    // ---- half 0: K then Q (heads 0-3) ----
    #pragma unroll
    for (int f=0;f<8;f++){accK[f][0]=0;accK[f][1]=0;accK[f][2]=0;accK[f][3]=0;}
    loadA(g_ak, j0);
    gemm_h(Pk_d, 0, accK);
    #pragma unroll
    for (int f=0;f<8;f++){accQ[f][0]=0;accQ[f][1]=0;accQ[f][2]=0;accQ[f][3]=0;}
    loadA(g_aq, j0 + d);
    gemm_h(Pq_d, 0, accQ);
    dots2_h(accQ, accK, 0);

    // ---- half 1: Q (sA still holds Aq) then K (heads 4-7) ----
    #pragma unroll
    for (int f=0;f<8;f++){accQ[f][0]=0;accQ[f][1]=0;accQ[f][2]=0;accQ[f][3]=0;}
    gemm_h(Pq_d, 64, accQ);
    #pragma unroll
    for (int f=0;f<8;f++){accK[f][0]=0;accK[f][1]=0;accK[f][2]=0;accK[f][3]=0;}
    loadA(g_ak, j0);
    gemm_h(Pk_d, 64, accK);
    dots2_h(accQ, accK, 1);

    // ---- V: full width, warp tile m32 x n64, acc[mf*8+nf][4] ----
    {
        int m_base = (warp&1)*32, n_base = (warp>>1)*64;
        float acc[16][4];
        #pragma unroll
        for (int f=0;f<16;f++){acc[f][0]=0;acc[f][1]=0;acc[f][2]=0;acc[f][3]=0;}
        loadA(g_av, j0);
        const float* P = Pv + (size_t)d*HD*HD;
        int pr = tid>>5, pc4 = tid&31;
        const float* Pt = P + pr*HD + pc4*4;
        float4 pre[4];
        #pragma unroll
        for (int q=0;q<4;q++) pre[q] = *(const float4*)(Pt + q*4*HD);
        for (int kc=0; kc<128; kc+=16) {
            __syncthreads();
            #pragma unroll
            for (int q=0;q<4;q++) {
                float4 v = pre[q];
                v.x=to_tf32(v.x); v.y=to_tf32(v.y); v.z=to_tf32(v.z); v.w=to_tf32(v.w);
                *(float4*)&sP[pr + q*4][pc4*4] = v;
            }
            __syncthreads();
            if (kc + 16 < 128) {
                #pragma unroll
                for (int q=0;q<4;q++) pre[q] = *(const float4*)(Pt + (kc+16)*HD + q*4*HD);
            }
            #pragma unroll
            for (int ks=0; ks<2; ks++) {
                int k0 = kc + ks*8;
                unsigned a[2][4];
                #pragma unroll
                for (int mf=0; mf<2; mf++) {
                    int mr = m_base + mf*16 + qrow;
                    a[mf][0] = __float_as_uint(sA[mr  ][k0+qcol  ]);
                    a[mf][1] = __float_as_uint(sA[mr+8][k0+qcol  ]);
                    a[mf][2] = __float_as_uint(sA[mr  ][k0+qcol+4]);
                    a[mf][3] = __float_as_uint(sA[mr+8][k0+qcol+4]);
                }
                #pragma unroll
                for (int nf=0; nf<8; nf++) {
                    unsigned b0 = __float_as_uint(sP[ks*8+qcol  ][n_base+nf*8+qrow]);
                    unsigned b1 = __float_as_uint(sP[ks*8+qcol+4][n_base+nf*8+qrow]);
                    mma_tf32(acc[nf],   a[0][0],a[0][1],a[0][2],a[0][3], b0,b1);
                    mma_tf32(acc[8+nf], a[1][0],a[1][1],a[1][2],a[1][3], b0,b1);
                }
            }
        }
        #pragma unroll
        for (int mf=0; mf<2; mf++) {
            #pragma unroll
            for (int nf=0; nf<8; nf++) {
                int col = n_base + nf*8 + 2*qcol;
                int r0 = m_base + mf*16 + qrow;
                if (r0 < nvalid)
                    *(float2*)(g_uv + ((size_t)d*SEQ + j0 + r0)*HD + col) = make_float2(acc[mf*8+nf][0], acc[mf*8+nf][1]);
                int r1 = r0 + 8;
                if (r1 < nvalid)
                    *(float2*)(g_uv + ((size_t)d*SEQ + j0 + r1)*HD + col) = make_float2(acc[mf*8+nf][2], acc[mf*8+nf][3]);
            }
        }
    }
}

// ---------------- dots1 + combine + causal softmax ----------------
__global__ void __launch_bounds__(256) attn_kernel() {
    int h  = blockIdx.y;
    int i0 = blockIdx.x * 16;
    __shared__ float sQ[16][68];
    __shared__ float sK[32][68];
    __shared__ float sD[16][512];
    int tid = threadIdx.x;
    {   int r = tid>>4, c4 = tid&15;
        *(float4*)&sQ[r][c4*4] = *(const float4*)(g_qkv + (i0+r)*1536 + h*64 + c4*4); }
    int r2 = tid>>4, jj = tid&15;
    for (int jc = 0; jc < 512; jc += 32) {
        __syncthreads();
        #pragma unroll
        for (int q=0; q<2; q++) {
            int idx = q*256 + tid; int r = idx>>4, c4 = idx&15;
            *(float4*)&sK[r][c4*4] = *(const float4*)(g_qkv + (jc+r)*1536 + 512 + h*64 + c4*4);
        }
        __syncthreads();
        float a0 = 0.f, a1 = 0.f;
        #pragma unroll
        for (int c=0; c<64; c++) {
            float qv = sQ[r2][c];
            a0 += qv * sK[jj][c];
            a1 += qv * sK[jj+16][c];
        }
        sD[r2][jc+jj]    = a0;
        sD[r2][jc+jj+16] = a1;
    }
    __syncthreads();
    int w = tid>>5, lane = tid&31;
    for (int rr = 2*w; rr < 2*w+2; rr++) {
        int i = i0 + rr;
        float vals[16];
        float m = -1e30f;
        #pragma unroll
        for (int t=0; t<16; t++) {
            int j = lane + t*32;
            float dv = -1e30f;
            if (j <= i)
                dv = 0.0625f * (sD[rr][j] + g_dots[(size_t)h*SEQ*SEQ + (size_t)i*SEQ + j]);
            vals[t] = dv;
            m = fmaxf(m, dv);
        }
        #pragma unroll
        for (int o=16;o;o>>=1) m = fmaxf(m, __shfl_xor_sync(0xffffffffu, m, o));
        float s = 0.f;
        #pragma unroll
        for (int t=0; t<16; t++) {
            float e = (vals[t] > -1e29f) ? __expf(vals[t]-m) : 0.f;
            vals[t] = e; s += e;
        }
        #pragma unroll
        for (int o=16;o;o>>=1) s += __shfl_xor_sync(0xffffffffu, s, o);
        float inv = 1.f / s;
        #pragma unroll
        for (int t=0; t<16; t++) {
            int j = lane + t*32;
            g_dots[(size_t)h*SEQ*SEQ + (size_t)i*SEQ + j] = vals[t]*inv;
        }
    }
}

// ---------------- out1 = attn @ v1 ----------------
__global__ void __launch_bounds__(256) out1_kernel() {
    int h = blockIdx.y, i0 = blockIdx.x*32;
    __shared__ float sAt[32][36];
    __shared__ float sV[32][68];
    int tid = threadIdx.x, ty = tid>>4, tx = tid&15;
    float acc[2][4] = {};
    for (int jc = 0; jc < 512; jc += 32) {
        __syncthreads();
        {   int r = tid>>3, c4 = tid&7;
            *(float4*)&sAt[r][c4*4] = *(const float4*)(g_dots + (size_t)h*SEQ*SEQ + (size_t)(i0+r)*512 + jc + c4*4); }
        #pragma unroll
        for (int q=0; q<2; q++) {
            int idx = q*256 + tid; int r = idx>>4, c4 = idx&15;
            *(float4*)&sV[r][c4*4] = *(const float4*)(g_qkv + (jc+r)*1536 + 1024 + h*64 + c4*4);
        }
        __syncthreads();
        #pragma unroll
        for (int k=0; k<32; k++) {
            float a0 = sAt[ty][k], a1 = sAt[ty+16][k];
            float4 v4 = *(float4*)&sV[k][tx*4];
            acc[0][0]+=a0*v4.x; acc[0][1]+=a0*v4.y; acc[0][2]+=a0*v4.z; acc[0][3]+=a0*v4.w;
            acc[1][0]+=a1*v4.x; acc[1][1]+=a1*v4.y; acc[1][2]+=a1*v4.z; acc[1][3]+=a1*v4.w;
        }
    }
    *(float4*)(g_out1 + (i0+ty)*512    + h*64 + tx*4) = make_float4(acc[0][0],acc[0][1],acc[0][2],acc[0][3]);
    *(float4*)(g_out1 + (i0+ty+16)*512 + h*64 + tx*4) = make_float4(acc[1][0],acc[1][1],acc[1][2],acc[1][3]);
}

// ---------------- out2[i,c] = sum_{j<=i} attn[h(c),i,j] * Uv[i-j][j][c] ----------------
__global__ void __launch_bounds__(512) out2_kernel() {
    int i = blockIdx.x;
    int tid = threadIdx.x;
    int c = tid & 127;
    int part = tid >> 7;
    int h = c >> 4;
    const float* arow = g_dots + (size_t)h*SEQ*SEQ + (size_t)i*SEQ;
    int len = i + 1;
    int chunk = (len + 3) >> 2;
    int jb = part*chunk, je = min(len, jb + chunk);
    float a0=0.f, a1=0.f, a2=0.f, a3=0.f;
    int j = jb;
    for (; j+4 <= je; j += 4) {
        a0 += arow[j]   * g_uv[((size_t)(i-j  )*SEQ + j  )*HD + c];
        a1 += arow[j+1] * g_uv[((size_t)(i-j-1)*SEQ + j+1)*HD + c];
        a2 += arow[j+2] * g_uv[((size_t)(i-j-2)*SEQ + j+2)*HD + c];
        a3 += arow[j+3] * g_uv[((size_t)(i-j-3)*SEQ + j+3)*HD + c];
    }
    for (; j < je; j++)
        a0 += arow[j] * g_uv[((size_t)(i-j)*SEQ + j)*HD + c];
    __shared__ float red[512];
    red[tid] = (a0+a1) + (a2+a3);
    __syncthreads();
    if (part == 0)
        g_out2[i*HD + c] = (red[c] + red[c+128]) + (red[c+256] + red[c+384]);
}

// ---------------- launch ----------------
extern "C" void kernel_launch(void* const* d_in, const int* in_sizes, int n_in,
                              void* d_out, int out_size) {
    const float* x     = (const float*)d_in[0];
    const float* ln_w  = (const float*)d_in[1];
    const float* ln_b  = (const float*)d_in[2];
    const float* w_qkv = (const float*)d_in[3];
    const float* w_q1  = (const float*)d_in[4];
    const float* p_q2  = (const float*)d_in[5];
    const float* w_k1  = (const float*)d_in[6];
    const float* p_k2  = (const float*)d_in[7];
    const float* w_v1  = (const float*)d_in[8];
    const float* p_v2  = (const float*)d_in[9];
    const float* w_v3  = (const float*)d_in[10];
    const float* w_out = (const float*)d_in[11];
    const float* b_out = (const float*)d_in[12];
    float* out = (float*)d_out;

    float *p_xn, *p_qkvb, *p_aq, *p_ak, *p_av, *p_out1b, *p_out2b, *p_tmpb;
    cudaGetSymbolAddress((void**)&p_xn,   g_xn);
    cudaGetSymbolAddress((void**)&p_qkvb, g_qkv);
    cudaGetSymbolAddress((void**)&p_aq,   g_aq);
    cudaGetSymbolAddress((void**)&p_ak,   g_ak);
    cudaGetSymbolAddress((void**)&p_av,   g_av);
    cudaGetSymbolAddress((void**)&p_out1b,g_out1);
    cudaGetSymbolAddress((void**)&p_out2b,g_out2);
    cudaGetSymbolAddress((void**)&p_tmpb, g_tmp);

    ln_kernel<<<512, 256>>>(x, ln_w, ln_b);

    // qkv = xn @ w_qkv  (512x1536x512)
    mma_gemm<0><<<dim3(24,8), 256>>>(p_xn, w_qkv, p_qkvb, 1536, 512, nullptr);
    // aq/ak/av = xn @ {w_q1,w_k1,w_v1}  (512x128x512, fused)
    mma_gemm3<<<dim3(2,8,3), 256>>>(p_xn, w_q1, w_k1, w_v1, p_aq, p_ak, p_av, 128, 512);

    diag_mma<<<dim3(8,512), 128>>>(p_q2, p_k2, p_v2);

    attn_kernel<<<dim3(32,8), 256>>>();
    out1_kernel<<<dim3(16,8), 256>>>();
    out2_kernel<<<512, 512>>>();

    // tmp = (out1 + out2 @ w_v3) * 0.5   (512x512x128)
    mma_gemm<1><<<dim3(8,8), 256>>>(p_out2b, w_v3, p_tmpb, 512, 128, p_out1b);
    // out = tmp @ w_out + b_out          (512x512x512)
    mma_gemm<2><<<dim3(8,8), 256>>>(p_tmpb, w_out, out, 512, 512, b_out);
}

// round 9
// speedup vs baseline: 1.0865x; 1.0191x over previous
#include <cuda_runtime.h>

#define SEQ   512
#define DIM   512
#define HEADS 8
#define DH    64
#define DR    16
#define HD    128

// ---------------- device scratch ----------------
__device__ float g_xn  [SEQ*DIM];
__device__ float g_qkv [SEQ*3*DIM];        // q1|k1|v1
__device__ float g_aq  [SEQ*HD];
__device__ float g_ak  [SEQ*HD];
__device__ float g_av  [SEQ*HD];
__device__ float g_dots[HEADS*SEQ*SEQ];    // dots2 lower-tri, then attn in place
__device__ float g_uv  [(size_t)SEQ*SEQ*HD];
__device__ float g_out1[SEQ*DIM];
__device__ float g_out2[SEQ*HD];
__device__ float g_tmp [SEQ*DIM];

// ---------------- helpers ----------------
__device__ __forceinline__ float to_tf32(float x) {
    unsigned u;
    asm("cvt.rna.tf32.f32 %0, %1;" : "=r"(u) : "f"(x));
    return __uint_as_float(u);
}
__device__ __forceinline__ void mma_tf32(float c[4], unsigned a0, unsigned a1, unsigned a2, unsigned a3,
                                         unsigned b0, unsigned b1) {
    asm volatile("mma.sync.aligned.m16n8k8.row.col.f32.tf32.tf32.f32 "
                 "{%0,%1,%2,%3}, {%4,%5,%6,%7}, {%8,%9}, {%0,%1,%2,%3};"
                 : "+f"(c[0]), "+f"(c[1]), "+f"(c[2]), "+f"(c[3])
                 : "r"(a0), "r"(a1), "r"(a2), "r"(a3), "r"(b0), "r"(b1));
}

// ---------------- layernorm ----------------
__global__ void __launch_bounds__(256) ln_kernel(const float* __restrict__ x,
                                                 const float* __restrict__ w,
                                                 const float* __restrict__ b) {
    int row = blockIdx.x;
    int tid = threadIdx.x;
    const float* xr = x + row*DIM;
    __shared__ float red[20];
    float v0 = xr[tid], v1 = xr[tid+256];
    float s = v0 + v1;
    #pragma unroll
    for (int o=16;o;o>>=1) s += __shfl_xor_sync(0xffffffffu, s, o);
    if ((tid&31)==0) red[tid>>5] = s;
    __syncthreads();
    if (tid < 8) {
        s = red[tid];
        #pragma unroll
        for (int o=4;o;o>>=1) s += __shfl_xor_sync(0xffu, s, o);
        if (tid==0) red[16] = s;
    }
    __syncthreads();
    float mu = red[16] * (1.0f/DIM);
    float d0 = v0-mu, d1 = v1-mu;
    float q = d0*d0 + d1*d1;
    #pragma unroll
    for (int o=16;o;o>>=1) q += __shfl_xor_sync(0xffffffffu, q, o);
    if ((tid&31)==0) red[8 + (tid>>5)] = q;
    __syncthreads();
    if (tid < 8) {
        q = red[8+tid];
        #pragma unroll
        for (int o=4;o;o>>=1) q += __shfl_xor_sync(0xffu, q, o);
        if (tid==0) red[17] = q;
    }
    __syncthreads();
    float inv = rsqrtf(red[17]*(1.0f/DIM) + 1e-5f);
    g_xn[row*DIM + tid]     = d0*inv*w[tid]     + b[tid];
    g_xn[row*DIM + tid+256] = d1*inv*w[tid+256] + b[tid+256];
}

// ---------------- generic tf32 MMA GEMM: C[M,N] = A[M,K] @ B[K,N], tile 64x64 ----------------
// sB padded to 72 (stride ≡ 8 mod 32) for conflict-free b-fragment LDS.
struct SmemGemm { float sA[64][36]; float sB[32][72]; };

template<int EPI>
__device__ __forceinline__ void gemm_body(const float* __restrict__ A, const float* __restrict__ B,
                                          float* __restrict__ C, int N, int K,
                                          const float* __restrict__ add,
                                          SmemGemm& sm, int m0, int n0) {
    int tid = threadIdx.x;
    int warp = tid>>5, lane = tid&31;
    int qrow = lane>>2, qcol = lane&3;
    int m_base = (warp&3)*16, n_base = (warp>>2)*32;
    float acc[4][4] = {};
    for (int kc = 0; kc < K; kc += 32) {
        __syncthreads();
        #pragma unroll
        for (int q=0;q<2;q++) {
            int idx = q*256+tid; int r = idx>>3, c4 = idx&7;
            float4 v = *(const float4*)(A + (m0+r)*K + kc + c4*4);
            sm.sA[r][c4*4+0]=to_tf32(v.x); sm.sA[r][c4*4+1]=to_tf32(v.y);
            sm.sA[r][c4*4+2]=to_tf32(v.z); sm.sA[r][c4*4+3]=to_tf32(v.w);
        }
        #pragma unroll
        for (int q=0;q<2;q++) {
            int idx = q*256+tid; int r = idx>>4, c4 = idx&15;
            float4 v = *(const float4*)(B + (kc+r)*N + n0 + c4*4);
            sm.sB[r][c4*4+0]=to_tf32(v.x); sm.sB[r][c4*4+1]=to_tf32(v.y);
            sm.sB[r][c4*4+2]=to_tf32(v.z); sm.sB[r][c4*4+3]=to_tf32(v.w);
        }
        __syncthreads();
        #pragma unroll
        for (int ks=0; ks<4; ks++) {
            int k0 = ks*8;
            unsigned a0 = __float_as_uint(sm.sA[m_base+qrow  ][k0+qcol  ]);
            unsigned a1 = __float_as_uint(sm.sA[m_base+qrow+8][k0+qcol  ]);
            unsigned a2 = __float_as_uint(sm.sA[m_base+qrow  ][k0+qcol+4]);
            unsigned a3 = __float_as_uint(sm.sA[m_base+qrow+8][k0+qcol+4]);
            #pragma unroll
            for (int nf=0; nf<4; nf++) {
                unsigned b0 = __float_as_uint(sm.sB[k0+qcol  ][n_base+nf*8+qrow]);
                unsigned b1 = __float_as_uint(sm.sB[k0+qcol+4][n_base+nf*8+qrow]);
                mma_tf32(acc[nf], a0,a1,a2,a3, b0,b1);
            }
        }
    }
    #pragma unroll
    for (int nf=0; nf<4; nf++) {
        int col = n0 + n_base + nf*8 + 2*qcol;
        int r0 = m0 + m_base + qrow, r1 = r0 + 8;
        float2 v0 = make_float2(acc[nf][0], acc[nf][1]);
        float2 v1 = make_float2(acc[nf][2], acc[nf][3]);
        if (EPI==1) {
            const float* p0 = add + (size_t)r0*N + col;
            const float* p1 = add + (size_t)r1*N + col;
            v0.x = (v0.x + p0[0])*0.5f; v0.y = (v0.y + p0[1])*0.5f;
            v1.x = (v1.x + p1[0])*0.5f; v1.y = (v1.y + p1[1])*0.5f;
        } else if (EPI==2) {
            v0.x += add[col]; v0.y += add[col+1];
            v1.x += add[col]; v1.y += add[col+1];
        }
        *(float2*)(C + (size_t)r0*N + col) = v0;
        *(float2*)(C + (size_t)r1*N + col) = v1;
    }
}

template<int EPI>
__global__ void __launch_bounds__(256) mma_gemm(const float* __restrict__ A, const float* __restrict__ B,
                                                float* __restrict__ C, int N, int K,
                                                const float* __restrict__ add) {
    __shared__ SmemGemm sm;
    gemm_body<EPI>(A, B, C, N, K, add, sm, blockIdx.y*64, blockIdx.x*64);
}

// fused q1/k1/v1 projections (z selects weight/output)
__global__ void __launch_bounds__(256) mma_gemm3(const float* __restrict__ A,
                                                 const float* __restrict__ B0, const float* __restrict__ B1,
                                                 const float* __restrict__ B2,
                                                 float* C0, float* C1, float* C2, int N, int K) {
    __shared__ SmemGemm sm;
    const float* B = blockIdx.z==0 ? B0 : (blockIdx.z==1 ? B1 : B2);
    float* C       = blockIdx.z==0 ? C0 : (blockIdx.z==1 ? C1 : C2);
    gemm_body<0>(A, B, C, N, K, nullptr, sm, blockIdx.y*64, blockIdx.x*64);
}

// ---------------- per-diagonal rel-projection via tf32 MMA ----------------
// Block: 256 threads = 8 warps; tile m128 x k128. Dynamic smem:
//   sA[128][132] (stride ≡4 mod 32: a-frags conflict-free)
//   sP[16][136]  (stride ≡8 mod 32: b-frags conflict-free)
// Warp grid 4m x 2n: m_base=(w&3)*32. Halves (n64): warp n32; V (n128): warp n64.
// Warps whose m-range is fully masked skip LDS/MMA via 'act' (still hit barriers).
#define DIAG_SMEM (128*132*4 + 16*136*4)

__global__ void __launch_bounds__(256,2) diag_mma(const float* __restrict__ Pq,
                                                  const float* __restrict__ Pk,
                                                  const float* __restrict__ Pv) {
    int d  = blockIdx.y;
    int nj = SEQ - d;
    int j0 = blockIdx.x * 128;
    if (j0 >= nj) return;
    int nvalid = min(128, nj - j0);

    extern __shared__ float dsm[];
    float (*sA)[132] = (float(*)[132])dsm;
    float (*sP)[136] = (float(*)[136])(dsm + 128*132);

    int tid = threadIdx.x, warp = tid>>5, lane = tid&31;
    int qrow = lane>>2, qcol = lane&3;
    int m_base = (warp&3)*32;
    bool act = m_base < nvalid;

    // guard previous MMA reads of sA, then refill (128 rows x 128 cols)
    auto loadA = [&](const float* __restrict__ Ab, int rowbase) {
        __syncthreads();
        #pragma unroll
        for (int q=0;q<16;q++) {
            int idx = q*256+tid; int r = idx>>5, c4 = idx&31;
            float4 v = make_float4(0.f,0.f,0.f,0.f);
            if (r < nvalid) v = *(const float4*)(Ab + (rowbase+r)*HD + c4*4);
            v.x=to_tf32(v.x); v.y=to_tf32(v.y); v.z=to_tf32(v.z); v.w=to_tf32(v.w);
            *(float4*)&sA[r][c4*4] = v;
        }
    };

    // ---- half-width gemm: B cols [c0, c0+64), warp tile m32 x n32 ----
    auto gemm_h = [&](const float* __restrict__ P, int c0, float acc[8][4]) {
        int n_base = (warp>>2)*32;
        // sP chunk fill: 16 rows x 64 cols = 256 float4, 1 per thread
        int pr = tid>>4, pc4 = tid&15;
        const float* Pt = P + pr*HD + c0 + pc4*4;
        float4 pre = *(const float4*)Pt;
        for (int kc=0; kc<128; kc+=16) {
            __syncthreads();
            {
                float4 v = pre;
                v.x=to_tf32(v.x); v.y=to_tf32(v.y); v.z=to_tf32(v.z); v.w=to_tf32(v.w);
                *(float4*)&sP[pr][pc4*4] = v;
            }
            __syncthreads();
            if (kc + 16 < 128) pre = *(const float4*)(Pt + (kc+16)*HD);
            if (act) {
                #pragma unroll
                for (int ks=0; ks<2; ks++) {
                    int k0 = kc + ks*8;
                    unsigned a[2][4];
                    #pragma unroll
                    for (int mf=0; mf<2; mf++) {
                        int mr = m_base + mf*16 + qrow;
                        a[mf][0] = __float_as_uint(sA[mr  ][k0+qcol  ]);
                        a[mf][1] = __float_as_uint(sA[mr+8][k0+qcol  ]);
                        a[mf][2] = __float_as_uint(sA[mr  ][k0+qcol+4]);
                        a[mf][3] = __float_as_uint(sA[mr+8][k0+qcol+4]);
                    }
                    #pragma unroll
                    for (int nf=0; nf<4; nf++) {
                        unsigned b0 = __float_as_uint(sP[ks*8+qcol  ][n_base+nf*8+qrow]);
                        unsigned b1 = __float_as_uint(sP[ks*8+qcol+4][n_base+nf*8+qrow]);
                        mma_tf32(acc[nf],   a[0][0],a[0][1],a[0][2],a[0][3], b0,b1);
                        mma_tf32(acc[4+nf], a[1][0],a[1][1],a[1][2],a[1][3], b0,b1);
                    }
                }
            }
        }
    };

    // dots2 epilogue for one half
    auto dots2_h = [&](float accQ[8][4], float accK[8][4], int half) {
        if (!act) return;
        #pragma unroll
        for (int mf=0; mf<2; mf++) {
            #pragma unroll
            for (int hh=0; hh<2; hh++) {
                int f0 = mf*4 + 2*hh, f1 = f0 + 1;
                float p0 = accQ[f0][0]*accK[f0][0] + accQ[f0][1]*accK[f0][1]
                         + accQ[f1][0]*accK[f1][0] + accQ[f1][1]*accK[f1][1];
                float p1 = accQ[f0][2]*accK[f0][2] + accQ[f0][3]*accK[f0][3]
                         + accQ[f1][2]*accK[f1][2] + accQ[f1][3]*accK[f1][3];
                p0 += __shfl_xor_sync(0xffffffffu, p0, 1);
                p0 += __shfl_xor_sync(0xffffffffu, p0, 2);
                p1 += __shfl_xor_sync(0xffffffffu, p1, 1);
                p1 += __shfl_xor_sync(0xffffffffu, p1, 2);
                if (qcol == 0) {
                    int h = half*4 + ((warp>>2)<<1) + hh;
                    int r0 = m_base + mf*16 + qrow;
                    if (r0 < nvalid) { int j = j0 + r0; g_dots[(size_t)h*SEQ*SEQ + (size_t)(j+d)*SEQ + j] = p0; }
                    int r1 = r0 + 8;
                    if (r1 < nvalid) { int j = j0 + r1; g_dots[(size_t)h*SEQ*SEQ + (size_t)(j+d)*SEQ + j] = p1; }
                }
            }
        }
    };

    const float* Pk_d = Pk + (size_t)d*HD*HD;
    const float* Pq_d = Pq + (size_t)(SEQ-1-d)*HD*HD;

    float accK[8][4], accQ[8][4];

    // ---- half 0 (heads 0-3): K then Q ----
    #pragma unroll
    for (int f=0;f<8;f++){accK[f][0]=0;accK[f][1]=0;accK[f][2]=0;accK[f][3]=0;}
    loadA(g_ak, j0);
    gemm_h(Pk_d, 0, accK);
    #pragma unroll
    for (int f=0;f<8;f++){accQ[f][0]=0;accQ[f][1]=0;accQ[f][2]=0;accQ[f][3]=0;}
    loadA(g_aq, j0 + d);
    gemm_h(Pq_d, 0, accQ);
    dots2_h(accQ, accK, 0);

    // ---- half 1 (heads 4-7): Q (sA holds Aq) then K ----
    #pragma unroll
    for (int f=0;f<8;f++){accQ[f][0]=0;accQ[f][1]=0;accQ[f][2]=0;accQ[f][3]=0;}
    gemm_h(Pq_d, 64, accQ);
    #pragma unroll
    for (int f=0;f<8;f++){accK[f][0]=0;accK[f][1]=0;accK[f][2]=0;accK[f][3]=0;}
    loadA(g_ak, j0);
    gemm_h(Pk_d, 64, accK);
    dots2_h(accQ, accK, 1);

    // ---- V: full n128, warp tile m32 x n64 ----
    {
        int n_base = (warp>>2)*64;
        float acc[16][4];
        #pragma unroll
        for (int f=0;f<16;f++){acc[f][0]=0;acc[f][1]=0;acc[f][2]=0;acc[f][3]=0;}
        loadA(g_av, j0);
        const float* P = Pv + (size_t)d*HD*HD;
        // sP chunk fill: 16 rows x 128 cols = 512 float4, 2 per thread
        int pr = tid>>5, pc4 = tid&31;
        const float* Pt = P + pr*HD + pc4*4;
        float4 pre[2];
        #pragma unroll
        for (int q=0;q<2;q++) pre[q] = *(const float4*)(Pt + q*8*HD);
        for (int kc=0; kc<128; kc+=16) {
            __syncthreads();
            #pragma unroll
            for (int q=0;q<2;q++) {
                float4 v = pre[q];
                v.x=to_tf32(v.x); v.y=to_tf32(v.y); v.z=to_tf32(v.z); v.w=to_tf32(v.w);
                *(float4*)&sP[pr + q*8][pc4*4] = v;
            }
            __syncthreads();
            if (kc + 16 < 128) {
                #pragma unroll
                for (int q=0;q<2;q++) pre[q] = *(const float4*)(Pt + (kc+16+q*8)*HD);
            }
            if (act) {
                #pragma unroll
                for (int ks=0; ks<2; ks++) {
                    int k0 = kc + ks*8;
                    unsigned a[2][4];
                    #pragma unroll
                    for (int mf=0; mf<2; mf++) {
                        int mr = m_base + mf*16 + qrow;
                        a[mf][0] = __float_as_uint(sA[mr  ][k0+qcol  ]);
                        a[mf][1] = __float_as_uint(sA[mr+8][k0+qcol  ]);
                        a[mf][2] = __float_as_uint(sA[mr  ][k0+qcol+4]);
                        a[mf][3] = __float_as_uint(sA[mr+8][k0+qcol+4]);
                    }
                    #pragma unroll
                    for (int nf=0; nf<8; nf++) {
                        unsigned b0 = __float_as_uint(sP[ks*8+qcol  ][n_base+nf*8+qrow]);
                        unsigned b1 = __float_as_uint(sP[ks*8+qcol+4][n_base+nf*8+qrow]);
                        mma_tf32(acc[nf],   a[0][0],a[0][1],a[0][2],a[0][3], b0,b1);
                        mma_tf32(acc[8+nf], a[1][0],a[1][1],a[1][2],a[1][3], b0,b1);
                    }
                }
            }
        }
        if (act) {
            #pragma unroll
            for (int mf=0; mf<2; mf++) {
                #pragma unroll
                for (int nf=0; nf<8; nf++) {
                    int col = n_base + nf*8 + 2*qcol;
                    int r0 = m_base + mf*16 + qrow;
                    if (r0 < nvalid)
                        *(float2*)(g_uv + ((size_t)d*SEQ + j0 + r0)*HD + col) = make_float2(acc[mf*8+nf][0], acc[mf*8+nf][1]);
                    int r1 = r0 + 8;
                    if (r1 < nvalid)
                        *(float2*)(g_uv + ((size_t)d*SEQ + j0 + r1)*HD + col) = make_float2(acc[mf*8+nf][2], acc[mf*8+nf][3]);
                }
            }
        }
    }
}

// ---------------- dots1 + combine + causal softmax ----------------
__global__ void __launch_bounds__(256) attn_kernel() {
    int h  = blockIdx.y;
    int i0 = blockIdx.x * 16;
    __shared__ float sQ[16][68];
    __shared__ float sK[32][68];
    __shared__ float sD[16][512];
    int tid = threadIdx.x;
    {   int r = tid>>4, c4 = tid&15;
        *(float4*)&sQ[r][c4*4] = *(const float4*)(g_qkv + (i0+r)*1536 + h*64 + c4*4); }
    int r2 = tid>>4, jj = tid&15;
    for (int jc = 0; jc < 512; jc += 32) {
        __syncthreads();
        #pragma unroll
        for (int q=0; q<2; q++) {
            int idx = q*256 + tid; int r = idx>>4, c4 = idx&15;
            *(float4*)&sK[r][c4*4] = *(const float4*)(g_qkv + (jc+r)*1536 + 512 + h*64 + c4*4);
        }
        __syncthreads();
        float a0 = 0.f, a1 = 0.f;
        #pragma unroll
        for (int c=0; c<64; c++) {
            float qv = sQ[r2][c];
            a0 += qv * sK[jj][c];
            a1 += qv * sK[jj+16][c];
        }
        sD[r2][jc+jj]    = a0;
        sD[r2][jc+jj+16] = a1;
    }
    __syncthreads();
    int w = tid>>5, lane = tid&31;
    for (int rr = 2*w; rr < 2*w+2; rr++) {
        int i = i0 + rr;
        float vals[16];
        float m = -1e30f;
        #pragma unroll
        for (int t=0; t<16; t++) {
            int j = lane + t*32;
            float dv = -1e30f;
            if (j <= i)
                dv = 0.0625f * (sD[rr][j] + g_dots[(size_t)h*SEQ*SEQ + (size_t)i*SEQ + j]);
            vals[t] = dv;
            m = fmaxf(m, dv);
        }
        #pragma unroll
        for (int o=16;o;o>>=1) m = fmaxf(m, __shfl_xor_sync(0xffffffffu, m, o));
        float s = 0.f;
        #pragma unroll
        for (int t=0; t<16; t++) {
            float e = (vals[t] > -1e29f) ? __expf(vals[t]-m) : 0.f;
            vals[t] = e; s += e;
        }
        #pragma unroll
        for (int o=16;o;o>>=1) s += __shfl_xor_sync(0xffffffffu, s, o);
        float inv = 1.f / s;
        #pragma unroll
        for (int t=0; t<16; t++) {
            int j = lane + t*32;
            g_dots[(size_t)h*SEQ*SEQ + (size_t)i*SEQ + j] = vals[t]*inv;
        }
    }
}

// ---------------- out1 = attn @ v1 ----------------
__global__ void __launch_bounds__(256) out1_kernel() {
    int h = blockIdx.y, i0 = blockIdx.x*32;
    __shared__ float sAt[32][36];
    __shared__ float sV[32][68];
    int tid = threadIdx.x, ty = tid>>4, tx = tid&15;
    float acc[2][4] = {};
    for (int jc = 0; jc < 512; jc += 32) {
        __syncthreads();
        {   int r = tid>>3, c4 = tid&7;
            *(float4*)&sAt[r][c4*4] = *(const float4*)(g_dots + (size_t)h*SEQ*SEQ + (size_t)(i0+r)*512 + jc + c4*4); }
        #pragma unroll
        for (int q=0; q<2; q++) {
            int idx = q*256 + tid; int r = idx>>4, c4 = idx&15;
            *(float4*)&sV[r][c4*4] = *(const float4*)(g_qkv + (jc+r)*1536 + 1024 + h*64 + c4*4);
        }
        __syncthreads();
        #pragma unroll
        for (int k=0; k<32; k++) {
            float a0 = sAt[ty][k], a1 = sAt[ty+16][k];
            float4 v4 = *(float4*)&sV[k][tx*4];
            acc[0][0]+=a0*v4.x; acc[0][1]+=a0*v4.y; acc[0][2]+=a0*v4.z; acc[0][3]+=a0*v4.w;
            acc[1][0]+=a1*v4.x; acc[1][1]+=a1*v4.y; acc[1][2]+=a1*v4.z; acc[1][3]+=a1*v4.w;
        }
    }
    *(float4*)(g_out1 + (i0+ty)*512    + h*64 + tx*4) = make_float4(acc[0][0],acc[0][1],acc[0][2],acc[0][3]);
    *(float4*)(g_out1 + (i0+ty+16)*512 + h*64 + tx*4) = make_float4(acc[1][0],acc[1][1],acc[1][2],acc[1][3]);
}

// ---------------- out2[i,c] = sum_{j<=i} attn[h(c),i,j] * Uv[i-j][j][c] ----------------
__global__ void __launch_bounds__(512) out2_kernel() {
    int i = blockIdx.x;
    int tid = threadIdx.x;
    int c = tid & 127;
    int part = tid >> 7;
    int h = c >> 4;
    const float* arow = g_dots + (size_t)h*SEQ*SEQ + (size_t)i*SEQ;
    int len = i + 1;
    int chunk = (len + 3) >> 2;
    int jb = part*chunk, je = min(len, jb + chunk);
    float a0=0.f, a1=0.f, a2=0.f, a3=0.f;
    int j = jb;
    for (; j+4 <= je; j += 4) {
        a0 += arow[j]   * g_uv[((size_t)(i-j  )*SEQ + j  )*HD + c];
        a1 += arow[j+1] * g_uv[((size_t)(i-j-1)*SEQ + j+1)*HD + c];
        a2 += arow[j+2] * g_uv[((size_t)(i-j-2)*SEQ + j+2)*HD + c];
        a3 += arow[j+3] * g_uv[((size_t)(i-j-3)*SEQ + j+3)*HD + c];
    }
    for (; j < je; j++)
        a0 += arow[j] * g_uv[((size_t)(i-j)*SEQ + j)*HD + c];
    __shared__ float red[512];
    red[tid] = (a0+a1) + (a2+a3);
    __syncthreads();
    if (part == 0)
        g_out2[i*HD + c] = (red[c] + red[c+128]) + (red[c+256] + red[c+384]);
}

// ---------------- launch ----------------
extern "C" void kernel_launch(void* const* d_in, const int* in_sizes, int n_in,
                              void* d_out, int out_size) {
    const float* x     = (const float*)d_in[0];
    const float* ln_w  = (const float*)d_in[1];
    const float* ln_b  = (const float*)d_in[2];
    const float* w_qkv = (const float*)d_in[3];
    const float* w_q1  = (const float*)d_in[4];
    const float* p_q2  = (const float*)d_in[5];
    const float* w_k1  = (const float*)d_in[6];
    const float* p_k2  = (const float*)d_in[7];
    const float* w_v1  = (const float*)d_in[8];
    const float* p_v2  = (const float*)d_in[9];
    const float* w_v3  = (const float*)d_in[10];
    const float* w_out = (const float*)d_in[11];
    const float* b_out = (const float*)d_in[12];
    float* out = (float*)d_out;

    float *p_xn, *p_qkvb, *p_aq, *p_ak, *p_av, *p_out1b, *p_out2b, *p_tmpb;
    cudaGetSymbolAddress((void**)&p_xn,   g_xn);
    cudaGetSymbolAddress((void**)&p_qkvb, g_qkv);
    cudaGetSymbolAddress((void**)&p_aq,   g_aq);
    cudaGetSymbolAddress((void**)&p_ak,   g_ak);
    cudaGetSymbolAddress((void**)&p_av,   g_av);
    cudaGetSymbolAddress((void**)&p_out1b,g_out1);
    cudaGetSymbolAddress((void**)&p_out2b,g_out2);
    cudaGetSymbolAddress((void**)&p_tmpb, g_tmp);

    // opt-in >48KB dynamic smem for diag_mma (idempotent; not a stream op)
    cudaFuncSetAttribute(diag_mma, cudaFuncAttributeMaxDynamicSharedMemorySize, DIAG_SMEM);

    ln_kernel<<<512, 256>>>(x, ln_w, ln_b);

    // qkv = xn @ w_qkv  (512x1536x512)
    mma_gemm<0><<<dim3(24,8), 256>>>(p_xn, w_qkv, p_qkvb, 1536, 512, nullptr);
    // aq/ak/av = xn @ {w_q1,w_k1,w_v1}  (512x128x512, fused)
    mma_gemm3<<<dim3(2,8,3), 256>>>(p_xn, w_q1, w_k1, w_v1, p_aq, p_ak, p_av, 128, 512);

    diag_mma<<<dim3(4,512), 256, DIAG_SMEM>>>(p_q2, p_k2, p_v2);

    attn_kernel<<<dim3(32,8), 256>>>();
    out1_kernel<<<dim3(16,8), 256>>>();
    out2_kernel<<<512, 512>>>();

    // tmp = (out1 + out2 @ w_v3) * 0.5   (512x512x128)
    mma_gemm<1><<<dim3(8,8), 256>>>(p_out2b, w_v3, p_tmpb, 512, 128, p_out1b);
    // out = tmp @ w_out + b_out          (512x512x512)
    mma_gemm<2><<<dim3(8,8), 256>>>(p_tmpb, w_out, out, 512, 512, b_out);
}

// round 10
// speedup vs baseline: 1.1076x; 1.0194x over previous
#include <cuda_runtime.h>

#define SEQ   512
#define DIM   512
#define HEADS 8
#define DH    64
#define DR    16
#define HD    128

// ---------------- device scratch ----------------
__device__ float g_xn  [SEQ*DIM];
__device__ float g_qkv [SEQ*3*DIM];        // q1|k1|v1
__device__ float g_aq  [SEQ*HD];
__device__ float g_ak  [SEQ*HD];
__device__ float g_av  [SEQ*HD];
__device__ float g_dots[HEADS*SEQ*SEQ];    // dots2 lower-tri, then attn in place
__device__ float g_uv  [(size_t)SEQ*SEQ*HD];
__device__ float g_out1[SEQ*DIM];
__device__ float g_out2[SEQ*HD];
__device__ float g_tmp [SEQ*DIM];

// ---------------- helpers ----------------
__device__ __forceinline__ float to_tf32(float x) {
    unsigned u;
    asm("cvt.rna.tf32.f32 %0, %1;" : "=r"(u) : "f"(x));
    return __uint_as_float(u);
}
__device__ __forceinline__ void mma_tf32(float c[4], unsigned a0, unsigned a1, unsigned a2, unsigned a3,
                                         unsigned b0, unsigned b1) {
    asm volatile("mma.sync.aligned.m16n8k8.row.col.f32.tf32.tf32.f32 "
                 "{%0,%1,%2,%3}, {%4,%5,%6,%7}, {%8,%9}, {%0,%1,%2,%3};"
                 : "+f"(c[0]), "+f"(c[1]), "+f"(c[2]), "+f"(c[3])
                 : "r"(a0), "r"(a1), "r"(a2), "r"(a3), "r"(b0), "r"(b1));
}

// ---------------- layernorm ----------------
__global__ void __launch_bounds__(256) ln_kernel(const float* __restrict__ x,
                                                 const float* __restrict__ w,
                                                 const float* __restrict__ b) {
    int row = blockIdx.x;
    int tid = threadIdx.x;
    const float* xr = x + row*DIM;
    __shared__ float red[20];
    float v0 = xr[tid], v1 = xr[tid+256];
    float s = v0 + v1;
    #pragma unroll
    for (int o=16;o;o>>=1) s += __shfl_xor_sync(0xffffffffu, s, o);
    if ((tid&31)==0) red[tid>>5] = s;
    __syncthreads();
    if (tid < 8) {
        s = red[tid];
        #pragma unroll
        for (int o=4;o;o>>=1) s += __shfl_xor_sync(0xffu, s, o);
        if (tid==0) red[16] = s;
    }
    __syncthreads();
    float mu = red[16] * (1.0f/DIM);
    float d0 = v0-mu, d1 = v1-mu;
    float q = d0*d0 + d1*d1;
    #pragma unroll
    for (int o=16;o;o>>=1) q += __shfl_xor_sync(0xffffffffu, q, o);
    if ((tid&31)==0) red[8 + (tid>>5)] = q;
    __syncthreads();
    if (tid < 8) {
        q = red[8+tid];
        #pragma unroll
        for (int o=4;o;o>>=1) q += __shfl_xor_sync(0xffu, q, o);
        if (tid==0) red[17] = q;
    }
    __syncthreads();
    float inv = rsqrtf(red[17]*(1.0f/DIM) + 1e-5f);
    g_xn[row*DIM + tid]     = d0*inv*w[tid]     + b[tid];
    g_xn[row*DIM + tid+256] = d1*inv*w[tid+256] + b[tid+256];
}

// ---------------- generic tf32 MMA GEMM: C[M,N] = A[M,K] @ B[K,N], tile 64x64 ----------------
// sB padded to 72 (stride ≡ 8 mod 32) for conflict-free b-fragment LDS.
struct SmemGemm { float sA[64][36]; float sB[32][72]; };

template<int EPI>
__device__ __forceinline__ void gemm_body(const float* __restrict__ A, const float* __restrict__ B,
                                          float* __restrict__ C, int N, int K,
                                          const float* __restrict__ add,
                                          SmemGemm& sm, int m0, int n0) {
    int tid = threadIdx.x;
    int warp = tid>>5, lane = tid&31;
    int qrow = lane>>2, qcol = lane&3;
    int m_base = (warp&3)*16, n_base = (warp>>2)*32;
    float acc[4][4] = {};
    for (int kc = 0; kc < K; kc += 32) {
        __syncthreads();
        #pragma unroll
        for (int q=0;q<2;q++) {
            int idx = q*256+tid; int r = idx>>3, c4 = idx&7;
            float4 v = *(const float4*)(A + (m0+r)*K + kc + c4*4);
            sm.sA[r][c4*4+0]=to_tf32(v.x); sm.sA[r][c4*4+1]=to_tf32(v.y);
            sm.sA[r][c4*4+2]=to_tf32(v.z); sm.sA[r][c4*4+3]=to_tf32(v.w);
        }
        #pragma unroll
        for (int q=0;q<2;q++) {
            int idx = q*256+tid; int r = idx>>4, c4 = idx&15;
            float4 v = *(const float4*)(B + (kc+r)*N + n0 + c4*4);
            sm.sB[r][c4*4+0]=to_tf32(v.x); sm.sB[r][c4*4+1]=to_tf32(v.y);
            sm.sB[r][c4*4+2]=to_tf32(v.z); sm.sB[r][c4*4+3]=to_tf32(v.w);
        }
        __syncthreads();
        #pragma unroll
        for (int ks=0; ks<4; ks++) {
            int k0 = ks*8;
            unsigned a0 = __float_as_uint(sm.sA[m_base+qrow  ][k0+qcol  ]);
            unsigned a1 = __float_as_uint(sm.sA[m_base+qrow+8][k0+qcol  ]);
            unsigned a2 = __float_as_uint(sm.sA[m_base+qrow  ][k0+qcol+4]);
            unsigned a3 = __float_as_uint(sm.sA[m_base+qrow+8][k0+qcol+4]);
            #pragma unroll
            for (int nf=0; nf<4; nf++) {
                unsigned b0 = __float_as_uint(sm.sB[k0+qcol  ][n_base+nf*8+qrow]);
                unsigned b1 = __float_as_uint(sm.sB[k0+qcol+4][n_base+nf*8+qrow]);
                mma_tf32(acc[nf], a0,a1,a2,a3, b0,b1);
            }
        }
    }
    #pragma unroll
    for (int nf=0; nf<4; nf++) {
        int col = n0 + n_base + nf*8 + 2*qcol;
        int r0 = m0 + m_base + qrow, r1 = r0 + 8;
        float2 v0 = make_float2(acc[nf][0], acc[nf][1]);
        float2 v1 = make_float2(acc[nf][2], acc[nf][3]);
        if (EPI==1) {
            const float* p0 = add + (size_t)r0*N + col;
            const float* p1 = add + (size_t)r1*N + col;
            v0.x = (v0.x + p0[0])*0.5f; v0.y = (v0.y + p0[1])*0.5f;
            v1.x = (v1.x + p1[0])*0.5f; v1.y = (v1.y + p1[1])*0.5f;
        } else if (EPI==2) {
            v0.x += add[col]; v0.y += add[col+1];
            v1.x += add[col]; v1.y += add[col+1];
        }
        *(float2*)(C + (size_t)r0*N + col) = v0;
        *(float2*)(C + (size_t)r1*N + col) = v1;
    }
}

template<int EPI>
__global__ void __launch_bounds__(256) mma_gemm(const float* __restrict__ A, const float* __restrict__ B,
                                                float* __restrict__ C, int N, int K,
                                                const float* __restrict__ add) {
    __shared__ SmemGemm sm;
    gemm_body<EPI>(A, B, C, N, K, add, sm, blockIdx.y*64, blockIdx.x*64);
}

// fused q1/k1/v1 projections (z selects weight/output)
__global__ void __launch_bounds__(256) mma_gemm3(const float* __restrict__ A,
                                                 const float* __restrict__ B0, const float* __restrict__ B1,
                                                 const float* __restrict__ B2,
                                                 float* C0, float* C1, float* C2, int N, int K) {
    __shared__ SmemGemm sm;
    const float* B = blockIdx.z==0 ? B0 : (blockIdx.z==1 ? B1 : B2);
    float* C       = blockIdx.z==0 ? C0 : (blockIdx.z==1 ? C1 : C2);
    gemm_body<0>(A, B, C, N, K, nullptr, sm, blockIdx.y*64, blockIdx.x*64);
}

// ---------------- per-diagonal rel-projection via tf32 MMA ----------------
// Block: 256 threads = 8 warps; tile m128 x k128. Dynamic smem:
//   sA[128][132]     (stride ≡4 mod 32: a-frags conflict-free)
//   sP[2][16][136]   (ping-pong; stride ≡8 mod 32: b-frags conflict-free)
// ONE __syncthreads per k-chunk: STS of chunk i+1 into buf nxt overlaps MMAs
// on buf cur; the barrier both publishes nxt and retires cur.
#define DIAG_SMEM (128*132*4 + 2*16*136*4)

__global__ void __launch_bounds__(256,2) diag_mma(const float* __restrict__ Pq,
                                                  const float* __restrict__ Pk,
                                                  const float* __restrict__ Pv) {
    int d  = blockIdx.y;
    int nj = SEQ - d;
    int j0 = blockIdx.x * 128;
    if (j0 >= nj) return;
    int nvalid = min(128, nj - j0);

    extern __shared__ float dsm[];
    float (*sA)[132] = (float(*)[132])dsm;
    float (*sP)[16][136] = (float(*)[16][136])(dsm + 128*132);

    int tid = threadIdx.x, warp = tid>>5, lane = tid&31;
    int qrow = lane>>2, qcol = lane&3;
    int m_base = (warp&3)*32;
    bool act = m_base < nvalid;

    // guard previous MMA reads of sA, then refill (128 rows x 128 cols)
    auto loadA = [&](const float* __restrict__ Ab, int rowbase) {
        __syncthreads();
        #pragma unroll
        for (int q=0;q<16;q++) {
            int idx = q*256+tid; int r = idx>>5, c4 = idx&31;
            float4 v = make_float4(0.f,0.f,0.f,0.f);
            if (r < nvalid) v = *(const float4*)(Ab + (rowbase+r)*HD + c4*4);
            v.x=to_tf32(v.x); v.y=to_tf32(v.y); v.z=to_tf32(v.z); v.w=to_tf32(v.w);
            *(float4*)&sA[r][c4*4] = v;
        }
    };

    // ---- half-width gemm: B cols [c0, c0+64), warp tile m32 x n32 ----
    auto gemm_h = [&](const float* __restrict__ P, int c0, float acc[8][4]) {
        int n_base = (warp>>2)*32;
        // sP chunk fill: 16 rows x 64 cols = 256 float4, 1 per thread
        int pr = tid>>4, pc4 = tid&15;
        const float* Pt = P + pr*HD + c0 + pc4*4;
        // prime: chunk 0 -> buf 0; prefetch chunk 1
        float4 pre = *(const float4*)Pt;
        {
            float4 v = pre;
            v.x=to_tf32(v.x); v.y=to_tf32(v.y); v.z=to_tf32(v.z); v.w=to_tf32(v.w);
            *(float4*)&sP[0][pr][pc4*4] = v;
        }
        pre = *(const float4*)(Pt + 16*HD);
        __syncthreads();   // publishes buf0 (and sA from loadA)
        int cur = 0;
        for (int kc=0; kc<128; kc+=16) {
            int nxt = cur^1;
            if (kc + 16 < 128) {
                float4 v = pre;
                v.x=to_tf32(v.x); v.y=to_tf32(v.y); v.z=to_tf32(v.z); v.w=to_tf32(v.w);
                *(float4*)&sP[nxt][pr][pc4*4] = v;
                if (kc + 32 < 128) pre = *(const float4*)(Pt + (kc+32)*HD);
            }
            if (act) {
                #pragma unroll
                for (int ks=0; ks<2; ks++) {
                    int k0 = kc + ks*8;
                    unsigned a[2][4];
                    #pragma unroll
                    for (int mf=0; mf<2; mf++) {
                        int mr = m_base + mf*16 + qrow;
                        a[mf][0] = __float_as_uint(sA[mr  ][k0+qcol  ]);
                        a[mf][1] = __float_as_uint(sA[mr+8][k0+qcol  ]);
                        a[mf][2] = __float_as_uint(sA[mr  ][k0+qcol+4]);
                        a[mf][3] = __float_as_uint(sA[mr+8][k0+qcol+4]);
                    }
                    #pragma unroll
                    for (int nf=0; nf<4; nf++) {
                        unsigned b0 = __float_as_uint(sP[cur][ks*8+qcol  ][n_base+nf*8+qrow]);
                        unsigned b1 = __float_as_uint(sP[cur][ks*8+qcol+4][n_base+nf*8+qrow]);
                        mma_tf32(acc[nf],   a[0][0],a[0][1],a[0][2],a[0][3], b0,b1);
                        mma_tf32(acc[4+nf], a[1][0],a[1][1],a[1][2],a[1][3], b0,b1);
                    }
                }
            }
            __syncthreads();   // publishes nxt; retires cur
            cur = nxt;
        }
    };

    // dots2 epilogue for one half
    auto dots2_h = [&](float accQ[8][4], float accK[8][4], int half) {
        if (!act) return;
        #pragma unroll
        for (int mf=0; mf<2; mf++) {
            #pragma unroll
            for (int hh=0; hh<2; hh++) {
                int f0 = mf*4 + 2*hh, f1 = f0 + 1;
                float p0 = accQ[f0][0]*accK[f0][0] + accQ[f0][1]*accK[f0][1]
                         + accQ[f1][0]*accK[f1][0] + accQ[f1][1]*accK[f1][1];
                float p1 = accQ[f0][2]*accK[f0][2] + accQ[f0][3]*accK[f0][3]
                         + accQ[f1][2]*accK[f1][2] + accQ[f1][3]*accK[f1][3];
                p0 += __shfl_xor_sync(0xffffffffu, p0, 1);
                p0 += __shfl_xor_sync(0xffffffffu, p0, 2);
                p1 += __shfl_xor_sync(0xffffffffu, p1, 1);
                p1 += __shfl_xor_sync(0xffffffffu, p1, 2);
                if (qcol == 0) {
                    int h = half*4 + ((warp>>2)<<1) + hh;
                    int r0 = m_base + mf*16 + qrow;
                    if (r0 < nvalid) { int j = j0 + r0; g_dots[(size_t)h*SEQ*SEQ + (size_t)(j+d)*SEQ + j] = p0; }
                    int r1 = r0 + 8;
                    if (r1 < nvalid) { int j = j0 + r1; g_dots[(size_t)h*SEQ*SEQ + (size_t)(j+d)*SEQ + j] = p1; }
                }
            }
        }
    };

    const float* Pk_d = Pk + (size_t)d*HD*HD;
    const float* Pq_d = Pq + (size_t)(SEQ-1-d)*HD*HD;

    float accK[8][4], accQ[8][4];

    // ---- half 0 (heads 0-3): K then Q ----
    #pragma unroll
    for (int f=0;f<8;f++){accK[f][0]=0;accK[f][1]=0;accK[f][2]=0;accK[f][3]=0;}
    loadA(g_ak, j0);
    gemm_h(Pk_d, 0, accK);
    #pragma unroll
    for (int f=0;f<8;f++){accQ[f][0]=0;accQ[f][1]=0;accQ[f][2]=0;accQ[f][3]=0;}
    loadA(g_aq, j0 + d);
    gemm_h(Pq_d, 0, accQ);
    dots2_h(accQ, accK, 0);

    // ---- half 1 (heads 4-7): Q (sA holds Aq) then K ----
    #pragma unroll
    for (int f=0;f<8;f++){accQ[f][0]=0;accQ[f][1]=0;accQ[f][2]=0;accQ[f][3]=0;}
    gemm_h(Pq_d, 64, accQ);
    #pragma unroll
    for (int f=0;f<8;f++){accK[f][0]=0;accK[f][1]=0;accK[f][2]=0;accK[f][3]=0;}
    loadA(g_ak, j0);
    gemm_h(Pk_d, 64, accK);
    dots2_h(accQ, accK, 1);

    // ---- V: full n128, warp tile m32 x n64 ----
    {
        int n_base = (warp>>2)*64;
        float acc[16][4];
        #pragma unroll
        for (int f=0;f<16;f++){acc[f][0]=0;acc[f][1]=0;acc[f][2]=0;acc[f][3]=0;}
        loadA(g_av, j0);
        const float* P = Pv + (size_t)d*HD*HD;
        // sP chunk fill: 16 rows x 128 cols = 512 float4, 2 per thread
        int pr = tid>>5, pc4 = tid&31;
        const float* Pt = P + pr*HD + pc4*4;
        float4 pre[2];
        #pragma unroll
        for (int q=0;q<2;q++) pre[q] = *(const float4*)(Pt + q*8*HD);
        #pragma unroll
        for (int q=0;q<2;q++) {
            float4 v = pre[q];
            v.x=to_tf32(v.x); v.y=to_tf32(v.y); v.z=to_tf32(v.z); v.w=to_tf32(v.w);
            *(float4*)&sP[0][pr + q*8][pc4*4] = v;
        }
        #pragma unroll
        for (int q=0;q<2;q++) pre[q] = *(const float4*)(Pt + (16 + q*8)*HD);
        __syncthreads();
        int cur = 0;
        for (int kc=0; kc<128; kc+=16) {
            int nxt = cur^1;
            if (kc + 16 < 128) {
                #pragma unroll
                for (int q=0;q<2;q++) {
                    float4 v = pre[q];
                    v.x=to_tf32(v.x); v.y=to_tf32(v.y); v.z=to_tf32(v.z); v.w=to_tf32(v.w);
                    *(float4*)&sP[nxt][pr + q*8][pc4*4] = v;
                }
                if (kc + 32 < 128) {
                    #pragma unroll
                    for (int q=0;q<2;q++) pre[q] = *(const float4*)(Pt + (kc+32+q*8)*HD);
                }
            }
            if (act) {
                #pragma unroll
                for (int ks=0; ks<2; ks++) {
                    int k0 = kc + ks*8;
                    unsigned a[2][4];
                    #pragma unroll
                    for (int mf=0; mf<2; mf++) {
                        int mr = m_base + mf*16 + qrow;
                        a[mf][0] = __float_as_uint(sA[mr  ][k0+qcol  ]);
                        a[mf][1] = __float_as_uint(sA[mr+8][k0+qcol  ]);
                        a[mf][2] = __float_as_uint(sA[mr  ][k0+qcol+4]);
                        a[mf][3] = __float_as_uint(sA[mr+8][k0+qcol+4]);
                    }
                    #pragma unroll
                    for (int nf=0; nf<8; nf++) {
                        unsigned b0 = __float_as_uint(sP[cur][ks*8+qcol  ][n_base+nf*8+qrow]);
                        unsigned b1 = __float_as_uint(sP[cur][ks*8+qcol+4][n_base+nf*8+qrow]);
                        mma_tf32(acc[nf],   a[0][0],a[0][1],a[0][2],a[0][3], b0,b1);
                        mma_tf32(acc[8+nf], a[1][0],a[1][1],a[1][2],a[1][3], b0,b1);
                    }
                }
            }
            __syncthreads();
            cur = nxt;
        }
        if (act) {
            #pragma unroll
            for (int mf=0; mf<2; mf++) {
                #pragma unroll
                for (int nf=0; nf<8; nf++) {
                    int col = n_base + nf*8 + 2*qcol;
                    int r0 = m_base + mf*16 + qrow;
                    if (r0 < nvalid)
                        *(float2*)(g_uv + ((size_t)d*SEQ + j0 + r0)*HD + col) = make_float2(acc[mf*8+nf][0], acc[mf*8+nf][1]);
                    int r1 = r0 + 8;
                    if (r1 < nvalid)
                        *(float2*)(g_uv + ((size_t)d*SEQ + j0 + r1)*HD + col) = make_float2(acc[mf*8+nf][2], acc[mf*8+nf][3]);
                }
            }
        }
    }
}

// ---------------- dots1 + combine + causal softmax ----------------
__global__ void __launch_bounds__(256) attn_kernel() {
    int h  = blockIdx.y;
    int i0 = blockIdx.x * 16;
    __shared__ float sQ[16][68];
    __shared__ float sK[32][68];
    __shared__ float sD[16][512];
    int tid = threadIdx.x;
    {   int r = tid>>4, c4 = tid&15;
        *(float4*)&sQ[r][c4*4] = *(const float4*)(g_qkv + (i0+r)*1536 + h*64 + c4*4); }
    int r2 = tid>>4, jj = tid&15;
    for (int jc = 0; jc < 512; jc += 32) {
        __syncthreads();
        #pragma unroll
        for (int q=0; q<2; q++) {
            int idx = q*256 + tid; int r = idx>>4, c4 = idx&15;
            *(float4*)&sK[r][c4*4] = *(const float4*)(g_qkv + (jc+r)*1536 + 512 + h*64 + c4*4);
        }
        __syncthreads();
        float a0 = 0.f, a1 = 0.f;
        #pragma unroll
        for (int c=0; c<64; c++) {
            float qv = sQ[r2][c];
            a0 += qv * sK[jj][c];
            a1 += qv * sK[jj+16][c];
        }
        sD[r2][jc+jj]    = a0;
        sD[r2][jc+jj+16] = a1;
    }
    __syncthreads();
    int w = tid>>5, lane = tid&31;
    for (int rr = 2*w; rr < 2*w+2; rr++) {
        int i = i0 + rr;
        float vals[16];
        float m = -1e30f;
        #pragma unroll
        for (int t=0; t<16; t++) {
            int j = lane + t*32;
            float dv = -1e30f;
            if (j <= i)
                dv = 0.0625f * (sD[rr][j] + g_dots[(size_t)h*SEQ*SEQ + (size_t)i*SEQ + j]);
            vals[t] = dv;
            m = fmaxf(m, dv);
        }
        #pragma unroll
        for (int o=16;o;o>>=1) m = fmaxf(m, __shfl_xor_sync(0xffffffffu, m, o));
        float s = 0.f;
        #pragma unroll
        for (int t=0; t<16; t++) {
            float e = (vals[t] > -1e29f) ? __expf(vals[t]-m) : 0.f;
            vals[t] = e; s += e;
        }
        #pragma unroll
        for (int o=16;o;o>>=1) s += __shfl_xor_sync(0xffffffffu, s, o);
        float inv = 1.f / s;
        #pragma unroll
        for (int t=0; t<16; t++) {
            int j = lane + t*32;
            g_dots[(size_t)h*SEQ*SEQ + (size_t)i*SEQ + j] = vals[t]*inv;
        }
    }
}

// ---------------- out1 = attn @ v1 ----------------
__global__ void __launch_bounds__(256) out1_kernel() {
    int h = blockIdx.y, i0 = blockIdx.x*32;
    __shared__ float sAt[32][36];
    __shared__ float sV[32][68];
    int tid = threadIdx.x, ty = tid>>4, tx = tid&15;
    float acc[2][4] = {};
    for (int jc = 0; jc < 512; jc += 32) {
        __syncthreads();
        {   int r = tid>>3, c4 = tid&7;
            *(float4*)&sAt[r][c4*4] = *(const float4*)(g_dots + (size_t)h*SEQ*SEQ + (size_t)(i0+r)*512 + jc + c4*4); }
        #pragma unroll
        for (int q=0; q<2; q++) {
            int idx = q*256 + tid; int r = idx>>4, c4 = idx&15;
            *(float4*)&sV[r][c4*4] = *(const float4*)(g_qkv + (jc+r)*1536 + 1024 + h*64 + c4*4);
        }
        __syncthreads();
        #pragma unroll
        for (int k=0; k<32; k++) {
            float a0 = sAt[ty][k], a1 = sAt[ty+16][k];
            float4 v4 = *(float4*)&sV[k][tx*4];
            acc[0][0]+=a0*v4.x; acc[0][1]+=a0*v4.y; acc[0][2]+=a0*v4.z; acc[0][3]+=a0*v4.w;
            acc[1][0]+=a1*v4.x; acc[1][1]+=a1*v4.y; acc[1][2]+=a1*v4.z; acc[1][3]+=a1*v4.w;
        }
    }
    *(float4*)(g_out1 + (i0+ty)*512    + h*64 + tx*4) = make_float4(acc[0][0],acc[0][1],acc[0][2],acc[0][3]);
    *(float4*)(g_out1 + (i0+ty+16)*512 + h*64 + tx*4) = make_float4(acc[1][0],acc[1][1],acc[1][2],acc[1][3]);
}

// ---------------- out2[i,c] = sum_{j<=i} attn[h(c),i,j] * Uv[i-j][j][c] ----------------
__global__ void __launch_bounds__(512) out2_kernel() {
    int i = blockIdx.x;
    int tid = threadIdx.x;
    int c = tid & 127;
    int part = tid >> 7;
    int h = c >> 4;
    const float* arow = g_dots + (size_t)h*SEQ*SEQ + (size_t)i*SEQ;
    int len = i + 1;
    int chunk = (len + 3) >> 2;
    int jb = part*chunk, je = min(len, jb + chunk);
    float a0=0.f, a1=0.f, a2=0.f, a3=0.f;
    int j = jb;
    for (; j+4 <= je; j += 4) {
        a0 += arow[j]   * g_uv[((size_t)(i-j  )*SEQ + j  )*HD + c];
        a1 += arow[j+1] * g_uv[((size_t)(i-j-1)*SEQ + j+1)*HD + c];
        a2 += arow[j+2] * g_uv[((size_t)(i-j-2)*SEQ + j+2)*HD + c];
        a3 += arow[j+3] * g_uv[((size_t)(i-j-3)*SEQ + j+3)*HD + c];
    }
    for (; j < je; j++)
        a0 += arow[j] * g_uv[((size_t)(i-j)*SEQ + j)*HD + c];
    __shared__ float red[512];
    red[tid] = (a0+a1) + (a2+a3);
    __syncthreads();
    if (part == 0)
        g_out2[i*HD + c] = (red[c] + red[c+128]) + (red[c+256] + red[c+384]);
}

// ---------------- launch ----------------
extern "C" void kernel_launch(void* const* d_in, const int* in_sizes, int n_in,
                              void* d_out, int out_size) {
    const float* x     = (const float*)d_in[0];
    const float* ln_w  = (const float*)d_in[1];
    const float* ln_b  = (const float*)d_in[2];
    const float* w_qkv = (const float*)d_in[3];
    const float* w_q1  = (const float*)d_in[4];
    const float* p_q2  = (const float*)d_in[5];
    const float* w_k1  = (const float*)d_in[6];
    const float* p_k2  = (const float*)d_in[7];
    const float* w_v1  = (const float*)d_in[8];
    const float* p_v2  = (const float*)d_in[9];
    const float* w_v3  = (const float*)d_in[10];
    const float* w_out = (const float*)d_in[11];
    const float* b_out = (const float*)d_in[12];
    float* out = (float*)d_out;

    float *p_xn, *p_qkvb, *p_aq, *p_ak, *p_av, *p_out1b, *p_out2b, *p_tmpb;
    cudaGetSymbolAddress((void**)&p_xn,   g_xn);
    cudaGetSymbolAddress((void**)&p_qkvb, g_qkv);
    cudaGetSymbolAddress((void**)&p_aq,   g_aq);
    cudaGetSymbolAddress((void**)&p_ak,   g_ak);
    cudaGetSymbolAddress((void**)&p_av,   g_av);
    cudaGetSymbolAddress((void**)&p_out1b,g_out1);
    cudaGetSymbolAddress((void**)&p_out2b,g_out2);
    cudaGetSymbolAddress((void**)&p_tmpb, g_tmp);

    // opt-in >48KB dynamic smem for diag_mma (idempotent; not a stream op)
    cudaFuncSetAttribute(diag_mma, cudaFuncAttributeMaxDynamicSharedMemorySize, DIAG_SMEM);

    ln_kernel<<<512, 256>>>(x, ln_w, ln_b);

    // qkv = xn @ w_qkv  (512x1536x512)
    mma_gemm<0><<<dim3(24,8), 256>>>(p_xn, w_qkv, p_qkvb, 1536, 512, nullptr);
    // aq/ak/av = xn @ {w_q1,w_k1,w_v1}  (512x128x512, fused)
    mma_gemm3<<<dim3(2,8,3), 256>>>(p_xn, w_q1, w_k1, w_v1, p_aq, p_ak, p_av, 128, 512);

    diag_mma<<<dim3(4,512), 256, DIAG_SMEM>>>(p_q2, p_k2, p_v2);

    attn_kernel<<<dim3(32,8), 256>>>();
    out1_kernel<<<dim3(16,8), 256>>>();
    out2_kernel<<<512, 512>>>();

    // tmp = (out1 + out2 @ w_v3) * 0.5   (512x512x128)
    mma_gemm<1><<<dim3(8,8), 256>>>(p_out2b, w_v3, p_tmpb, 512, 128, p_out1b);
    // out = tmp @ w_out + b_out          (512x512x512)
    mma_gemm<2><<<dim3(8,8), 256>>>(p_tmpb, w_out, out, 512, 512, b_out);
}

// round 11
// speedup vs baseline: 1.1212x; 1.0123x over previous
#include <cuda_runtime.h>

#define SEQ   512
#define DIM   512
#define HEADS 8
#define DH    64
#define DR    16
#define HD    128

// ---------------- device scratch ----------------
__device__ float g_xn  [SEQ*DIM];
__device__ float g_qkv [SEQ*3*DIM];        // q1|k1|v1
__device__ float g_aq  [SEQ*HD];
__device__ float g_ak  [SEQ*HD];
__device__ float g_av  [SEQ*HD];
__device__ float g_dots[HEADS*SEQ*SEQ];    // dots2 lower-tri, then attn in place
__device__ float g_uv  [(size_t)SEQ*SEQ*HD];
__device__ float g_out1[SEQ*DIM];
__device__ float g_out2[SEQ*HD];
__device__ float g_tmp [SEQ*DIM];

// ---------------- helpers ----------------
__device__ __forceinline__ float to_tf32(float x) {
    unsigned u;
    asm("cvt.rna.tf32.f32 %0, %1;" : "=r"(u) : "f"(x));
    return __uint_as_float(u);
}
__device__ __forceinline__ void mma_tf32(float c[4], unsigned a0, unsigned a1, unsigned a2, unsigned a3,
                                         unsigned b0, unsigned b1) {
    asm volatile("mma.sync.aligned.m16n8k8.row.col.f32.tf32.tf32.f32 "
                 "{%0,%1,%2,%3}, {%4,%5,%6,%7}, {%8,%9}, {%0,%1,%2,%3};"
                 : "+f"(c[0]), "+f"(c[1]), "+f"(c[2]), "+f"(c[3])
                 : "r"(a0), "r"(a1), "r"(a2), "r"(a3), "r"(b0), "r"(b1));
}

// ---------------- layernorm ----------------
__global__ void __launch_bounds__(256) ln_kernel(const float* __restrict__ x,
                                                 const float* __restrict__ w,
                                                 const float* __restrict__ b) {
    int row = blockIdx.x;
    int tid = threadIdx.x;
    const float* xr = x + row*DIM;
    __shared__ float red[20];
    float v0 = xr[tid], v1 = xr[tid+256];
    float s = v0 + v1;
    #pragma unroll
    for (int o=16;o;o>>=1) s += __shfl_xor_sync(0xffffffffu, s, o);
    if ((tid&31)==0) red[tid>>5] = s;
    __syncthreads();
    if (tid < 8) {
        s = red[tid];
        #pragma unroll
        for (int o=4;o;o>>=1) s += __shfl_xor_sync(0xffu, s, o);
        if (tid==0) red[16] = s;
    }
    __syncthreads();
    float mu = red[16] * (1.0f/DIM);
    float d0 = v0-mu, d1 = v1-mu;
    float q = d0*d0 + d1*d1;
    #pragma unroll
    for (int o=16;o;o>>=1) q += __shfl_xor_sync(0xffffffffu, q, o);
    if ((tid&31)==0) red[8 + (tid>>5)] = q;
    __syncthreads();
    if (tid < 8) {
        q = red[8+tid];
        #pragma unroll
        for (int o=4;o;o>>=1) q += __shfl_xor_sync(0xffu, q, o);
        if (tid==0) red[17] = q;
    }
    __syncthreads();
    float inv = rsqrtf(red[17]*(1.0f/DIM) + 1e-5f);
    g_xn[row*DIM + tid]     = d0*inv*w[tid]     + b[tid];
    g_xn[row*DIM + tid+256] = d1*inv*w[tid+256] + b[tid+256];
}

// ---------------- generic tf32 MMA GEMM: C[M,N] = A[M,K] @ B[K,N], tile 64x64 ----------------
struct SmemGemm { float sA[64][36]; float sB[32][72]; };

template<int EPI>
__device__ __forceinline__ void gemm_body(const float* __restrict__ A, const float* __restrict__ B,
                                          float* __restrict__ C, int N, int K,
                                          const float* __restrict__ add,
                                          SmemGemm& sm, int m0, int n0) {
    int tid = threadIdx.x;
    int warp = tid>>5, lane = tid&31;
    int qrow = lane>>2, qcol = lane&3;
    int m_base = (warp&3)*16, n_base = (warp>>2)*32;
    float acc[4][4] = {};
    for (int kc = 0; kc < K; kc += 32) {
        __syncthreads();
        #pragma unroll
        for (int q=0;q<2;q++) {
            int idx = q*256+tid; int r = idx>>3, c4 = idx&7;
            float4 v = *(const float4*)(A + (m0+r)*K + kc + c4*4);
            sm.sA[r][c4*4+0]=to_tf32(v.x); sm.sA[r][c4*4+1]=to_tf32(v.y);
            sm.sA[r][c4*4+2]=to_tf32(v.z); sm.sA[r][c4*4+3]=to_tf32(v.w);
        }
        #pragma unroll
        for (int q=0;q<2;q++) {
            int idx = q*256+tid; int r = idx>>4, c4 = idx&15;
            float4 v = *(const float4*)(B + (kc+r)*N + n0 + c4*4);
            sm.sB[r][c4*4+0]=to_tf32(v.x); sm.sB[r][c4*4+1]=to_tf32(v.y);
            sm.sB[r][c4*4+2]=to_tf32(v.z); sm.sB[r][c4*4+3]=to_tf32(v.w);
        }
        __syncthreads();
        #pragma unroll
        for (int ks=0; ks<4; ks++) {
            int k0 = ks*8;
            unsigned a0 = __float_as_uint(sm.sA[m_base+qrow  ][k0+qcol  ]);
            unsigned a1 = __float_as_uint(sm.sA[m_base+qrow+8][k0+qcol  ]);
            unsigned a2 = __float_as_uint(sm.sA[m_base+qrow  ][k0+qcol+4]);
            unsigned a3 = __float_as_uint(sm.sA[m_base+qrow+8][k0+qcol+4]);
            #pragma unroll
            for (int nf=0; nf<4; nf++) {
                unsigned b0 = __float_as_uint(sm.sB[k0+qcol  ][n_base+nf*8+qrow]);
                unsigned b1 = __float_as_uint(sm.sB[k0+qcol+4][n_base+nf*8+qrow]);
                mma_tf32(acc[nf], a0,a1,a2,a3, b0,b1);
            }
        }
    }
    #pragma unroll
    for (int nf=0; nf<4; nf++) {
        int col = n0 + n_base + nf*8 + 2*qcol;
        int r0 = m0 + m_base + qrow, r1 = r0 + 8;
        float2 v0 = make_float2(acc[nf][0], acc[nf][1]);
        float2 v1 = make_float2(acc[nf][2], acc[nf][3]);
        if (EPI==1) {
            const float* p0 = add + (size_t)r0*N + col;
            const float* p1 = add + (size_t)r1*N + col;
            v0.x = (v0.x + p0[0])*0.5f; v0.y = (v0.y + p0[1])*0.5f;
            v1.x = (v1.x + p1[0])*0.5f; v1.y = (v1.y + p1[1])*0.5f;
        } else if (EPI==2) {
            v0.x += add[col]; v0.y += add[col+1];
            v1.x += add[col]; v1.y += add[col+1];
        }
        *(float2*)(C + (size_t)r0*N + col) = v0;
        *(float2*)(C + (size_t)r1*N + col) = v1;
    }
}

template<int EPI>
__global__ void __launch_bounds__(256) mma_gemm(const float* __restrict__ A, const float* __restrict__ B,
                                                float* __restrict__ C, int N, int K,
                                                const float* __restrict__ add) {
    __shared__ SmemGemm sm;
    gemm_body<EPI>(A, B, C, N, K, add, sm, blockIdx.y*64, blockIdx.x*64);
}

// fused q1/k1/v1 projections (z selects weight/output)
__global__ void __launch_bounds__(256) mma_gemm3(const float* __restrict__ A,
                                                 const float* __restrict__ B0, const float* __restrict__ B1,
                                                 const float* __restrict__ B2,
                                                 float* C0, float* C1, float* C2, int N, int K) {
    __shared__ SmemGemm sm;
    const float* B = blockIdx.z==0 ? B0 : (blockIdx.z==1 ? B1 : B2);
    float* C       = blockIdx.z==0 ? C0 : (blockIdx.z==1 ? C1 : C2);
    gemm_body<0>(A, B, C, N, K, nullptr, sm, blockIdx.y*64, blockIdx.x*64);
}

// ---------------- per-diagonal rel-projection via tf32 MMA ----------------
// Block: 256 threads = 8 warps; tile m128 x k128.
// sA[128][132] row-major (a-frags scalar LDS, conflict-free).
// P panel stored FRAGMENT-MAJOR in ping-pong buffers:
//   element (k, n) -> row' = (ks*2+khalf)*32 + qrow*4 + kq,  col' = nf
//   (ks=k>>3, khalf=(k>>2)&1, kq=k&3, qrow=n&7, nf=n>>3)
//   row stride 12 floats (halves, nf 0..7) / 20 floats (V, nf 0..15).
// => b-fragments for 4 consecutive nf come from ONE LDS.128 at
//    ((ks*2+khalf)*32 + lane)*stride + nf0  — conflict-free, 16B-aligned.
#define PBUF_FLOATS 2560                    // 128 rows' x 20 (V worst case)
#define DIAG_SMEM (128*132*4 + 2*PBUF_FLOATS*4)

__global__ void __launch_bounds__(256,2) diag_mma(const float* __restrict__ Pq,
                                                  const float* __restrict__ Pk,
                                                  const float* __restrict__ Pv) {
    int d  = blockIdx.y;
    int nj = SEQ - d;
    int j0 = blockIdx.x * 128;
    if (j0 >= nj) return;
    int nvalid = min(128, nj - j0);

    extern __shared__ float dsm[];
    float (*sA)[132] = (float(*)[132])dsm;
    float* sB = dsm + 128*132;              // two PBUF_FLOATS buffers

    int tid = threadIdx.x, warp = tid>>5, lane = tid&31;
    int qrow = lane>>2, qcol = lane&3;
    int m_base = (warp&3)*32;
    bool act = m_base < nvalid;

    auto loadA = [&](const float* __restrict__ Ab, int rowbase) {
        __syncthreads();
        #pragma unroll
        for (int q=0;q<16;q++) {
            int idx = q*256+tid; int r = idx>>5, c4 = idx&31;
            float4 v = make_float4(0.f,0.f,0.f,0.f);
            if (r < nvalid) v = *(const float4*)(Ab + (rowbase+r)*HD + c4*4);
            v.x=to_tf32(v.x); v.y=to_tf32(v.y); v.z=to_tf32(v.z); v.w=to_tf32(v.w);
            *(float4*)&sA[r][c4*4] = v;
        }
    };

    // ---- half-width gemm: B cols [c0, c0+64), warp tile m32 x n32 ----
    auto gemm_h = [&](const float* __restrict__ P, int c0, float acc[8][4]) {
        int nf0 = (warp>>2)*4;
        // fill mapping: thread -> (k row pr 0..15, float4 at n=4L)
        int pr = tid>>4, L = tid&15;
        const float* Pt = P + pr*HD + c0 + L*4;
        int rowbase_f = ((pr>>3)*2 + ((pr>>2)&1))*32 + (pr&3);
        int nf_f = L>>1;
        int qoff = (L&1)*4;
        auto stchunk = [&](float* buf, float4 v) {
            buf[(rowbase_f + (qoff+0)*4)*12 + nf_f] = to_tf32(v.x);
            buf[(rowbase_f + (qoff+1)*4)*12 + nf_f] = to_tf32(v.y);
            buf[(rowbase_f + (qoff+2)*4)*12 + nf_f] = to_tf32(v.z);
            buf[(rowbase_f + (qoff+3)*4)*12 + nf_f] = to_tf32(v.w);
        };
        float4 pre = *(const float4*)Pt;
        stchunk(sB, pre);
        pre = *(const float4*)(Pt + 16*HD);
        __syncthreads();                     // publishes buf0 (and sA)
        int cur = 0;
        for (int kc=0; kc<128; kc+=16) {
            int nxt = cur^1;
            if (kc + 16 < 128) {
                stchunk(sB + nxt*PBUF_FLOATS, pre);
                if (kc + 32 < 128) pre = *(const float4*)(Pt + (kc+32)*HD);
            }
            if (act) {
                const float* buf = sB + cur*PBUF_FLOATS;
                #pragma unroll
                for (int ks=0; ks<2; ks++) {
                    int k0 = kc + ks*8;
                    unsigned a[2][4];
                    #pragma unroll
                    for (int mf=0; mf<2; mf++) {
                        int mr = m_base + mf*16 + qrow;
                        a[mf][0] = __float_as_uint(sA[mr  ][k0+qcol  ]);
                        a[mf][1] = __float_as_uint(sA[mr+8][k0+qcol  ]);
                        a[mf][2] = __float_as_uint(sA[mr  ][k0+qcol+4]);
                        a[mf][3] = __float_as_uint(sA[mr+8][k0+qcol+4]);
                    }
                    float4 b0p = *(const float4*)(buf + ((ks*2+0)*32 + lane)*12 + nf0);
                    float4 b1p = *(const float4*)(buf + ((ks*2+1)*32 + lane)*12 + nf0);
                    const float* b0a = (const float*)&b0p;
                    const float* b1a = (const float*)&b1p;
                    #pragma unroll
                    for (int nf=0; nf<4; nf++) {
                        unsigned b0 = __float_as_uint(b0a[nf]);
                        unsigned b1 = __float_as_uint(b1a[nf]);
                        mma_tf32(acc[nf],   a[0][0],a[0][1],a[0][2],a[0][3], b0,b1);
                        mma_tf32(acc[4+nf], a[1][0],a[1][1],a[1][2],a[1][3], b0,b1);
                    }
                }
            }
            __syncthreads();
            cur = nxt;
        }
    };

    // dots2 epilogue for one half
    auto dots2_h = [&](float accQ[8][4], float accK[8][4], int half) {
        if (!act) return;
        #pragma unroll
        for (int mf=0; mf<2; mf++) {
            #pragma unroll
            for (int hh=0; hh<2; hh++) {
                int f0 = mf*4 + 2*hh, f1 = f0 + 1;
                float p0 = accQ[f0][0]*accK[f0][0] + accQ[f0][1]*accK[f0][1]
                         + accQ[f1][0]*accK[f1][0] + accQ[f1][1]*accK[f1][1];
                float p1 = accQ[f0][2]*accK[f0][2] + accQ[f0][3]*accK[f0][3]
                         + accQ[f1][2]*accK[f1][2] + accQ[f1][3]*accK[f1][3];
                p0 += __shfl_xor_sync(0xffffffffu, p0, 1);
                p0 += __shfl_xor_sync(0xffffffffu, p0, 2);
                p1 += __shfl_xor_sync(0xffffffffu, p1, 1);
                p1 += __shfl_xor_sync(0xffffffffu, p1, 2);
                if (qcol == 0) {
                    int h = half*4 + ((warp>>2)<<1) + hh;
                    int r0 = m_base + mf*16 + qrow;
                    if (r0 < nvalid) { int j = j0 + r0; g_dots[(size_t)h*SEQ*SEQ + (size_t)(j+d)*SEQ + j] = p0; }
                    int r1 = r0 + 8;
                    if (r1 < nvalid) { int j = j0 + r1; g_dots[(size_t)h*SEQ*SEQ + (size_t)(j+d)*SEQ + j] = p1; }
                }
            }
        }
    };

    const float* Pk_d = Pk + (size_t)d*HD*HD;
    const float* Pq_d = Pq + (size_t)(SEQ-1-d)*HD*HD;

    float accK[8][4], accQ[8][4];

    // ---- half 0 (heads 0-3): K then Q ----
    #pragma unroll
    for (int f=0;f<8;f++){accK[f][0]=0;accK[f][1]=0;accK[f][2]=0;accK[f][3]=0;}
    loadA(g_ak, j0);
    gemm_h(Pk_d, 0, accK);
    #pragma unroll
    for (int f=0;f<8;f++){accQ[f][0]=0;accQ[f][1]=0;accQ[f][2]=0;accQ[f][3]=0;}
    loadA(g_aq, j0 + d);
    gemm_h(Pq_d, 0, accQ);
    dots2_h(accQ, accK, 0);

    // ---- half 1 (heads 4-7): Q (sA holds Aq) then K ----
    #pragma unroll
    for (int f=0;f<8;f++){accQ[f][0]=0;accQ[f][1]=0;accQ[f][2]=0;accQ[f][3]=0;}
    gemm_h(Pq_d, 64, accQ);
    #pragma unroll
    for (int f=0;f<8;f++){accK[f][0]=0;accK[f][1]=0;accK[f][2]=0;accK[f][3]=0;}
    loadA(g_ak, j0);
    gemm_h(Pk_d, 64, accK);
    dots2_h(accQ, accK, 1);

    // ---- V: full n128, warp tile m32 x n64, fragment-major stride 20 ----
    {
        int nf0 = (warp>>2)*8;
        float acc[16][4];
        #pragma unroll
        for (int f=0;f<16;f++){acc[f][0]=0;acc[f][1]=0;acc[f][2]=0;acc[f][3]=0;}
        loadA(g_av, j0);
        const float* P = Pv + (size_t)d*HD*HD;
        // fill: thread -> k rows {pr, pr+8}, float4 at n=4*pc4
        int pr = tid>>5, pc4 = tid&31;
        const float* Pt = P + pr*HD + pc4*4;
        int khalf_f = (pr>>2)&1, kq_f = pr&3;
        int nf_f = pc4>>1;
        int qoff = (pc4&1)*4;
        auto stchunkV = [&](float* buf, float4 v, int q) {
            int rowbase_f = (q*2 + khalf_f)*32 + kq_f;   // ks = q for rows pr+8q
            buf[(rowbase_f + (qoff+0)*4)*20 + nf_f] = to_tf32(v.x);
            buf[(rowbase_f + (qoff+1)*4)*20 + nf_f] = to_tf32(v.y);
            buf[(rowbase_f + (qoff+2)*4)*20 + nf_f] = to_tf32(v.z);
            buf[(rowbase_f + (qoff+3)*4)*20 + nf_f] = to_tf32(v.w);
        };
        float4 pre[2];
        #pragma unroll
        for (int q=0;q<2;q++) pre[q] = *(const float4*)(Pt + q*8*HD);
        #pragma unroll
        for (int q=0;q<2;q++) stchunkV(sB, pre[q], q);
        #pragma unroll
        for (int q=0;q<2;q++) pre[q] = *(const float4*)(Pt + (16 + q*8)*HD);
        __syncthreads();
        int cur = 0;
        for (int kc=0; kc<128; kc+=16) {
            int nxt = cur^1;
            if (kc + 16 < 128) {
                #pragma unroll
                for (int q=0;q<2;q++) stchunkV(sB + nxt*PBUF_FLOATS, pre[q], q);
                if (kc + 32 < 128) {
                    #pragma unroll
                    for (int q=0;q<2;q++) pre[q] = *(const float4*)(Pt + (kc+32+q*8)*HD);
                }
            }
            if (act) {
                const float* buf = sB + cur*PBUF_FLOATS;
                #pragma unroll
                for (int ks=0; ks<2; ks++) {
                    int k0 = kc + ks*8;
                    unsigned a[2][4];
                    #pragma unroll
                    for (int mf=0; mf<2; mf++) {
                        int mr = m_base + mf*16 + qrow;
                        a[mf][0] = __float_as_uint(sA[mr  ][k0+qcol  ]);
                        a[mf][1] = __float_as_uint(sA[mr+8][k0+qcol  ]);
                        a[mf][2] = __float_as_uint(sA[mr  ][k0+qcol+4]);
                        a[mf][3] = __float_as_uint(sA[mr+8][k0+qcol+4]);
                    }
                    float4 b0p0 = *(const float4*)(buf + ((ks*2+0)*32 + lane)*20 + nf0);
                    float4 b0p1 = *(const float4*)(buf + ((ks*2+0)*32 + lane)*20 + nf0 + 4);
                    float4 b1p0 = *(const float4*)(buf + ((ks*2+1)*32 + lane)*20 + nf0);
                    float4 b1p1 = *(const float4*)(buf + ((ks*2+1)*32 + lane)*20 + nf0 + 4);
                    const float* b0a = (const float*)&b0p0;   // [0..3] then b0p1 [0..3]
                    const float* b0b = (const float*)&b0p1;
                    const float* b1a = (const float*)&b1p0;
                    const float* b1b = (const float*)&b1p1;
                    #pragma unroll
                    for (int nf=0; nf<8; nf++) {
                        unsigned b0 = __float_as_uint(nf < 4 ? b0a[nf] : b0b[nf-4]);
                        unsigned b1 = __float_as_uint(nf < 4 ? b1a[nf] : b1b[nf-4]);
                        mma_tf32(acc[nf],   a[0][0],a[0][1],a[0][2],a[0][3], b0,b1);
                        mma_tf32(acc[8+nf], a[1][0],a[1][1],a[1][2],a[1][3], b0,b1);
                    }
                }
            }
            __syncthreads();
            cur = nxt;
        }
        if (act) {
            int n_base = (warp>>2)*64;
            #pragma unroll
            for (int mf=0; mf<2; mf++) {
                #pragma unroll
                for (int nf=0; nf<8; nf++) {
                    int col = n_base + nf*8 + 2*qcol;
                    int r0 = m_base + mf*16 + qrow;
                    if (r0 < nvalid)
                        *(float2*)(g_uv + ((size_t)d*SEQ + j0 + r0)*HD + col) = make_float2(acc[mf*8+nf][0], acc[mf*8+nf][1]);
                    int r1 = r0 + 8;
                    if (r1 < nvalid)
                        *(float2*)(g_uv + ((size_t)d*SEQ + j0 + r1)*HD + col) = make_float2(acc[mf*8+nf][2], acc[mf*8+nf][3]);
                }
            }
        }
    }
}

// ---------------- dots1 + combine + causal softmax ----------------
__global__ void __launch_bounds__(256) attn_kernel() {
    int h  = blockIdx.y;
    int i0 = blockIdx.x * 16;
    __shared__ float sQ[16][68];
    __shared__ float sK[32][68];
    __shared__ float sD[16][512];
    int tid = threadIdx.x;
    {   int r = tid>>4, c4 = tid&15;
        *(float4*)&sQ[r][c4*4] = *(const float4*)(g_qkv + (i0+r)*1536 + h*64 + c4*4); }
    int r2 = tid>>4, jj = tid&15;
    for (int jc = 0; jc < 512; jc += 32) {
        __syncthreads();
        #pragma unroll
        for (int q=0; q<2; q++) {
            int idx = q*256 + tid; int r = idx>>4, c4 = idx&15;
            *(float4*)&sK[r][c4*4] = *(const float4*)(g_qkv + (jc+r)*1536 + 512 + h*64 + c4*4);
        }
        __syncthreads();
        float a0 = 0.f, a1 = 0.f;
        #pragma unroll
        for (int c=0; c<64; c++) {
            float qv = sQ[r2][c];
            a0 += qv * sK[jj][c];
            a1 += qv * sK[jj+16][c];
        }
        sD[r2][jc+jj]    = a0;
        sD[r2][jc+jj+16] = a1;
    }
    __syncthreads();
    int w = tid>>5, lane = tid&31;
    for (int rr = 2*w; rr < 2*w+2; rr++) {
        int i = i0 + rr;
        float vals[16];
        float m = -1e30f;
        #pragma unroll
        for (int t=0; t<16; t++) {
            int j = lane + t*32;
            float dv = -1e30f;
            if (j <= i)
                dv = 0.0625f * (sD[rr][j] + g_dots[(size_t)h*SEQ*SEQ + (size_t)i*SEQ + j]);
            vals[t] = dv;
            m = fmaxf(m, dv);
        }
        #pragma unroll
        for (int o=16;o;o>>=1) m = fmaxf(m, __shfl_xor_sync(0xffffffffu, m, o));
        float s = 0.f;
        #pragma unroll
        for (int t=0; t<16; t++) {
            float e = (vals[t] > -1e29f) ? __expf(vals[t]-m) : 0.f;
            vals[t] = e; s += e;
        }
        #pragma unroll
        for (int o=16;o;o>>=1) s += __shfl_xor_sync(0xffffffffu, s, o);
        float inv = 1.f / s;
        #pragma unroll
        for (int t=0; t<16; t++) {
            int j = lane + t*32;
            g_dots[(size_t)h*SEQ*SEQ + (size_t)i*SEQ + j] = vals[t]*inv;
        }
    }
}

// ---------------- out1 = attn @ v1 ----------------
__global__ void __launch_bounds__(256) out1_kernel() {
    int h = blockIdx.y, i0 = blockIdx.x*32;
    __shared__ float sAt[32][36];
    __shared__ float sV[32][68];
    int tid = threadIdx.x, ty = tid>>4, tx = tid&15;
    float acc[2][4] = {};
    for (int jc = 0; jc < 512; jc += 32) {
        __syncthreads();
        {   int r = tid>>3, c4 = tid&7;
            *(float4*)&sAt[r][c4*4] = *(const float4*)(g_dots + (size_t)h*SEQ*SEQ + (size_t)(i0+r)*512 + jc + c4*4); }
        #pragma unroll
        for (int q=0; q<2; q++) {
            int idx = q*256 + tid; int r = idx>>4, c4 = idx&15;
            *(float4*)&sV[r][c4*4] = *(const float4*)(g_qkv + (jc+r)*1536 + 1024 + h*64 + c4*4);
        }
        __syncthreads();
        #pragma unroll
        for (int k=0; k<32; k++) {
            float a0 = sAt[ty][k], a1 = sAt[ty+16][k];
            float4 v4 = *(float4*)&sV[k][tx*4];
            acc[0][0]+=a0*v4.x; acc[0][1]+=a0*v4.y; acc[0][2]+=a0*v4.z; acc[0][3]+=a0*v4.w;
            acc[1][0]+=a1*v4.x; acc[1][1]+=a1*v4.y; acc[1][2]+=a1*v4.z; acc[1][3]+=a1*v4.w;
        }
    }
    *(float4*)(g_out1 + (i0+ty)*512    + h*64 + tx*4) = make_float4(acc[0][0],acc[0][1],acc[0][2],acc[0][3]);
    *(float4*)(g_out1 + (i0+ty+16)*512 + h*64 + tx*4) = make_float4(acc[1][0],acc[1][1],acc[1][2],acc[1][3]);
}

// ---------------- out2[i,c] = sum_{j<=i} attn[h(c),i,j] * Uv[i-j][j][c] ----------------
__global__ void __launch_bounds__(512) out2_kernel() {
    int i = blockIdx.x;
    int tid = threadIdx.x;
    int c = tid & 127;
    int part = tid >> 7;
    int h = c >> 4;
    const float* arow = g_dots + (size_t)h*SEQ*SEQ + (size_t)i*SEQ;
    int len = i + 1;
    int chunk = (len + 3) >> 2;
    int jb = part*chunk, je = min(len, jb + chunk);
    float a0=0.f, a1=0.f, a2=0.f, a3=0.f;
    int j = jb;
    for (; j+4 <= je; j += 4) {
        a0 += arow[j]   * g_uv[((size_t)(i-j  )*SEQ + j  )*HD + c];
        a1 += arow[j+1] * g_uv[((size_t)(i-j-1)*SEQ + j+1)*HD + c];
        a2 += arow[j+2] * g_uv[((size_t)(i-j-2)*SEQ + j+2)*HD + c];
        a3 += arow[j+3] * g_uv[((size_t)(i-j-3)*SEQ + j+3)*HD + c];
    }
    for (; j < je; j++)
        a0 += arow[j] * g_uv[((size_t)(i-j)*SEQ + j)*HD + c];
    __shared__ float red[512];
    red[tid] = (a0+a1) + (a2+a3);
    __syncthreads();
    if (part == 0)
        g_out2[i*HD + c] = (red[c] + red[c+128]) + (red[c+256] + red[c+384]);
}

// ---------------- launch ----------------
extern "C" void kernel_launch(void* const* d_in, const int* in_sizes, int n_in,
                              void* d_out, int out_size) {
    const float* x     = (const float*)d_in[0];
    const float* ln_w  = (const float*)d_in[1];
    const float* ln_b  = (const float*)d_in[2];
    const float* w_qkv = (const float*)d_in[3];
    const float* w_q1  = (const float*)d_in[4];
    const float* p_q2  = (const float*)d_in[5];
    const float* w_k1  = (const float*)d_in[6];
    const float* p_k2  = (const float*)d_in[7];
    const float* w_v1  = (const float*)d_in[8];
    const float* p_v2  = (const float*)d_in[9];
    const float* w_v3  = (const float*)d_in[10];
    const float* w_out = (const float*)d_in[11];
    const float* b_out = (const float*)d_in[12];
    float* out = (float*)d_out;

    float *p_xn, *p_qkvb, *p_aq, *p_ak, *p_av, *p_out1b, *p_out2b, *p_tmpb;
    cudaGetSymbolAddress((void**)&p_xn,   g_xn);
    cudaGetSymbolAddress((void**)&p_qkvb, g_qkv);
    cudaGetSymbolAddress((void**)&p_aq,   g_aq);
    cudaGetSymbolAddress((void**)&p_ak,   g_ak);
    cudaGetSymbolAddress((void**)&p_av,   g_av);
    cudaGetSymbolAddress((void**)&p_out1b,g_out1);
    cudaGetSymbolAddress((void**)&p_out2b,g_out2);
    cudaGetSymbolAddress((void**)&p_tmpb, g_tmp);

    // opt-in >48KB dynamic smem for diag_mma (idempotent; not a stream op)
    cudaFuncSetAttribute(diag_mma, cudaFuncAttributeMaxDynamicSharedMemorySize, DIAG_SMEM);

    ln_kernel<<<512, 256>>>(x, ln_w, ln_b);

    // qkv = xn @ w_qkv  (512x1536x512)
    mma_gemm<0><<<dim3(24,8), 256>>>(p_xn, w_qkv, p_qkvb, 1536, 512, nullptr);
    // aq/ak/av = xn @ {w_q1,w_k1,w_v1}  (512x128x512, fused)
    mma_gemm3<<<dim3(2,8,3), 256>>>(p_xn, w_q1, w_k1, w_v1, p_aq, p_ak, p_av, 128, 512);

    diag_mma<<<dim3(4,512), 256, DIAG_SMEM>>>(p_q2, p_k2, p_v2);

    attn_kernel<<<dim3(32,8), 256>>>();
    out1_kernel<<<dim3(16,8), 256>>>();
    out2_kernel<<<512, 512>>>();

    // tmp = (out1 + out2 @ w_v3) * 0.5   (512x512x128)
    mma_gemm<1><<<dim3(8,8), 256>>>(p_out2b, w_v3, p_tmpb, 512, 128, p_out1b);
    // out = tmp @ w_out + b_out          (512x512x512)
    mma_gemm<2><<<dim3(8,8), 256>>>(p_tmpb, w_out, out, 512, 512, b_out);
}

// round 12
// speedup vs baseline: 1.1290x; 1.0070x over previous
#include <cuda_runtime.h>

#define SEQ   512
#define DIM   512
#define HEADS 8
#define DH    64
#define DR    16
#define HD    128

// ---------------- device scratch ----------------
__device__ float g_xn  [SEQ*DIM];
__device__ float g_qkv [SEQ*3*DIM];        // q1|k1|v1
__device__ float g_aq  [SEQ*HD];
__device__ float g_ak  [SEQ*HD];
__device__ float g_av  [SEQ*HD];
__device__ float g_dots[HEADS*SEQ*SEQ];    // dots2 lower-tri, then attn in place
__device__ float g_uv  [(size_t)SEQ*SEQ*HD];
__device__ float g_out1[SEQ*DIM];
__device__ float g_out2[SEQ*HD];
__device__ float g_tmp [SEQ*DIM];

// ---------------- helpers ----------------
__device__ __forceinline__ float to_tf32(float x) {
    unsigned u;
    asm("cvt.rna.tf32.f32 %0, %1;" : "=r"(u) : "f"(x));
    return __uint_as_float(u);
}
__device__ __forceinline__ void mma_tf32(float c[4], unsigned a0, unsigned a1, unsigned a2, unsigned a3,
                                         unsigned b0, unsigned b1) {
    asm volatile("mma.sync.aligned.m16n8k8.row.col.f32.tf32.tf32.f32 "
                 "{%0,%1,%2,%3}, {%4,%5,%6,%7}, {%8,%9}, {%0,%1,%2,%3};"
                 : "+f"(c[0]), "+f"(c[1]), "+f"(c[2]), "+f"(c[3])
                 : "r"(a0), "r"(a1), "r"(a2), "r"(a3), "r"(b0), "r"(b1));
}

// ---------------- layernorm ----------------
__global__ void __launch_bounds__(256) ln_kernel(const float* __restrict__ x,
                                                 const float* __restrict__ w,
                                                 const float* __restrict__ b) {
    int row = blockIdx.x;
    int tid = threadIdx.x;
    const float* xr = x + row*DIM;
    __shared__ float red[20];
    float v0 = xr[tid], v1 = xr[tid+256];
    float s = v0 + v1;
    #pragma unroll
    for (int o=16;o;o>>=1) s += __shfl_xor_sync(0xffffffffu, s, o);
    if ((tid&31)==0) red[tid>>5] = s;
    __syncthreads();
    if (tid < 8) {
        s = red[tid];
        #pragma unroll
        for (int o=4;o;o>>=1) s += __shfl_xor_sync(0xffu, s, o);
        if (tid==0) red[16] = s;
    }
    __syncthreads();
    float mu = red[16] * (1.0f/DIM);
    float d0 = v0-mu, d1 = v1-mu;
    float q = d0*d0 + d1*d1;
    #pragma unroll
    for (int o=16;o;o>>=1) q += __shfl_xor_sync(0xffffffffu, q, o);
    if ((tid&31)==0) red[8 + (tid>>5)] = q;
    __syncthreads();
    if (tid < 8) {
        q = red[8+tid];
        #pragma unroll
        for (int o=4;o;o>>=1) q += __shfl_xor_sync(0xffu, q, o);
        if (tid==0) red[17] = q;
    }
    __syncthreads();
    float inv = rsqrtf(red[17]*(1.0f/DIM) + 1e-5f);
    g_xn[row*DIM + tid]     = d0*inv*w[tid]     + b[tid];
    g_xn[row*DIM + tid+256] = d1*inv*w[tid+256] + b[tid+256];
}

// ---------------- generic tf32 MMA GEMM: C[M,N] = A[M,K] @ B[K,N], tile 64x64 ----------------
struct SmemGemm { float sA[64][36]; float sB[32][72]; };

template<int EPI>
__device__ __forceinline__ void gemm_body(const float* __restrict__ A, const float* __restrict__ B,
                                          float* __restrict__ C, int N, int K,
                                          const float* __restrict__ add,
                                          SmemGemm& sm, int m0, int n0) {
    int tid = threadIdx.x;
    int warp = tid>>5, lane = tid&31;
    int qrow = lane>>2, qcol = lane&3;
    int m_base = (warp&3)*16, n_base = (warp>>2)*32;
    float acc[4][4] = {};
    for (int kc = 0; kc < K; kc += 32) {
        __syncthreads();
        #pragma unroll
        for (int q=0;q<2;q++) {
            int idx = q*256+tid; int r = idx>>3, c4 = idx&7;
            float4 v = *(const float4*)(A + (m0+r)*K + kc + c4*4);
            sm.sA[r][c4*4+0]=to_tf32(v.x); sm.sA[r][c4*4+1]=to_tf32(v.y);
            sm.sA[r][c4*4+2]=to_tf32(v.z); sm.sA[r][c4*4+3]=to_tf32(v.w);
        }
        #pragma unroll
        for (int q=0;q<2;q++) {
            int idx = q*256+tid; int r = idx>>4, c4 = idx&15;
            float4 v = *(const float4*)(B + (kc+r)*N + n0 + c4*4);
            sm.sB[r][c4*4+0]=to_tf32(v.x); sm.sB[r][c4*4+1]=to_tf32(v.y);
            sm.sB[r][c4*4+2]=to_tf32(v.z); sm.sB[r][c4*4+3]=to_tf32(v.w);
        }
        __syncthreads();
        #pragma unroll
        for (int ks=0; ks<4; ks++) {
            int k0 = ks*8;
            unsigned a0 = __float_as_uint(sm.sA[m_base+qrow  ][k0+qcol  ]);
            unsigned a1 = __float_as_uint(sm.sA[m_base+qrow+8][k0+qcol  ]);
            unsigned a2 = __float_as_uint(sm.sA[m_base+qrow  ][k0+qcol+4]);
            unsigned a3 = __float_as_uint(sm.sA[m_base+qrow+8][k0+qcol+4]);
            #pragma unroll
            for (int nf=0; nf<4; nf++) {
                unsigned b0 = __float_as_uint(sm.sB[k0+qcol  ][n_base+nf*8+qrow]);
                unsigned b1 = __float_as_uint(sm.sB[k0+qcol+4][n_base+nf*8+qrow]);
                mma_tf32(acc[nf], a0,a1,a2,a3, b0,b1);
            }
        }
    }
    #pragma unroll
    for (int nf=0; nf<4; nf++) {
        int col = n0 + n_base + nf*8 + 2*qcol;
        int r0 = m0 + m_base + qrow, r1 = r0 + 8;
        float2 v0 = make_float2(acc[nf][0], acc[nf][1]);
        float2 v1 = make_float2(acc[nf][2], acc[nf][3]);
        if (EPI==1) {
            const float* p0 = add + (size_t)r0*N + col;
            const float* p1 = add + (size_t)r1*N + col;
            v0.x = (v0.x + p0[0])*0.5f; v0.y = (v0.y + p0[1])*0.5f;
            v1.x = (v1.x + p1[0])*0.5f; v1.y = (v1.y + p1[1])*0.5f;
        } else if (EPI==2) {
            v0.x += add[col]; v0.y += add[col+1];
            v1.x += add[col]; v1.y += add[col+1];
        }
        *(float2*)(C + (size_t)r0*N + col) = v0;
        *(float2*)(C + (size_t)r1*N + col) = v1;
    }
}

template<int EPI>
__global__ void __launch_bounds__(256) mma_gemm(const float* __restrict__ A, const float* __restrict__ B,
                                                float* __restrict__ C, int N, int K,
                                                const float* __restrict__ add) {
    __shared__ SmemGemm sm;
    gemm_body<EPI>(A, B, C, N, K, add, sm, blockIdx.y*64, blockIdx.x*64);
}

// fused q1/k1/v1 projections (z selects weight/output)
__global__ void __launch_bounds__(256) mma_gemm3(const float* __restrict__ A,
                                                 const float* __restrict__ B0, const float* __restrict__ B1,
                                                 const float* __restrict__ B2,
                                                 float* C0, float* C1, float* C2, int N, int K) {
    __shared__ SmemGemm sm;
    const float* B = blockIdx.z==0 ? B0 : (blockIdx.z==1 ? B1 : B2);
    float* C       = blockIdx.z==0 ? C0 : (blockIdx.z==1 ? C1 : C2);
    gemm_body<0>(A, B, C, N, K, nullptr, sm, blockIdx.y*64, blockIdx.x*64);
}

// ---------------- per-diagonal rel-projection via tf32 MMA ----------------
// (unchanged from R11 — frozen at ~170us)
#define PBUF_FLOATS 2560
#define DIAG_SMEM (128*132*4 + 2*PBUF_FLOATS*4)

__global__ void __launch_bounds__(256,2) diag_mma(const float* __restrict__ Pq,
                                                  const float* __restrict__ Pk,
                                                  const float* __restrict__ Pv) {
    int d  = blockIdx.y;
    int nj = SEQ - d;
    int j0 = blockIdx.x * 128;
    if (j0 >= nj) return;
    int nvalid = min(128, nj - j0);

    extern __shared__ float dsm[];
    float (*sA)[132] = (float(*)[132])dsm;
    float* sB = dsm + 128*132;

    int tid = threadIdx.x, warp = tid>>5, lane = tid&31;
    int qrow = lane>>2, qcol = lane&3;
    int m_base = (warp&3)*32;
    bool act = m_base < nvalid;

    auto loadA = [&](const float* __restrict__ Ab, int rowbase) {
        __syncthreads();
        #pragma unroll
        for (int q=0;q<16;q++) {
            int idx = q*256+tid; int r = idx>>5, c4 = idx&31;
            float4 v = make_float4(0.f,0.f,0.f,0.f);
            if (r < nvalid) v = *(const float4*)(Ab + (rowbase+r)*HD + c4*4);
            v.x=to_tf32(v.x); v.y=to_tf32(v.y); v.z=to_tf32(v.z); v.w=to_tf32(v.w);
            *(float4*)&sA[r][c4*4] = v;
        }
    };

    auto gemm_h = [&](const float* __restrict__ P, int c0, float acc[8][4]) {
        int nf0 = (warp>>2)*4;
        int pr = tid>>4, L = tid&15;
        const float* Pt = P + pr*HD + c0 + L*4;
        int rowbase_f = ((pr>>3)*2 + ((pr>>2)&1))*32 + (pr&3);
        int nf_f = L>>1;
        int qoff = (L&1)*4;
        auto stchunk = [&](float* buf, float4 v) {
            buf[(rowbase_f + (qoff+0)*4)*12 + nf_f] = to_tf32(v.x);
            buf[(rowbase_f + (qoff+1)*4)*12 + nf_f] = to_tf32(v.y);
            buf[(rowbase_f + (qoff+2)*4)*12 + nf_f] = to_tf32(v.z);
            buf[(rowbase_f + (qoff+3)*4)*12 + nf_f] = to_tf32(v.w);
        };
        float4 pre = *(const float4*)Pt;
        stchunk(sB, pre);
        pre = *(const float4*)(Pt + 16*HD);
        __syncthreads();
        int cur = 0;
        for (int kc=0; kc<128; kc+=16) {
            int nxt = cur^1;
            if (kc + 16 < 128) {
                stchunk(sB + nxt*PBUF_FLOATS, pre);
                if (kc + 32 < 128) pre = *(const float4*)(Pt + (kc+32)*HD);
            }
            if (act) {
                const float* buf = sB + cur*PBUF_FLOATS;
                #pragma unroll
                for (int ks=0; ks<2; ks++) {
                    int k0 = kc + ks*8;
                    unsigned a[2][4];
                    #pragma unroll
                    for (int mf=0; mf<2; mf++) {
                        int mr = m_base + mf*16 + qrow;
                        a[mf][0] = __float_as_uint(sA[mr  ][k0+qcol  ]);
                        a[mf][1] = __float_as_uint(sA[mr+8][k0+qcol  ]);
                        a[mf][2] = __float_as_uint(sA[mr  ][k0+qcol+4]);
                        a[mf][3] = __float_as_uint(sA[mr+8][k0+qcol+4]);
                    }
                    float4 b0p = *(const float4*)(buf + ((ks*2+0)*32 + lane)*12 + nf0);
                    float4 b1p = *(const float4*)(buf + ((ks*2+1)*32 + lane)*12 + nf0);
                    const float* b0a = (const float*)&b0p;
                    const float* b1a = (const float*)&b1p;
                    #pragma unroll
                    for (int nf=0; nf<4; nf++) {
                        unsigned b0 = __float_as_uint(b0a[nf]);
                        unsigned b1 = __float_as_uint(b1a[nf]);
                        mma_tf32(acc[nf],   a[0][0],a[0][1],a[0][2],a[0][3], b0,b1);
                        mma_tf32(acc[4+nf], a[1][0],a[1][1],a[1][2],a[1][3], b0,b1);
                    }
                }
            }
            __syncthreads();
            cur = nxt;
        }
    };

    auto dots2_h = [&](float accQ[8][4], float accK[8][4], int half) {
        if (!act) return;
        #pragma unroll
        for (int mf=0; mf<2; mf++) {
            #pragma unroll
            for (int hh=0; hh<2; hh++) {
                int f0 = mf*4 + 2*hh, f1 = f0 + 1;
                float p0 = accQ[f0][0]*accK[f0][0] + accQ[f0][1]*accK[f0][1]
                         + accQ[f1][0]*accK[f1][0] + accQ[f1][1]*accK[f1][1];
                float p1 = accQ[f0][2]*accK[f0][2] + accQ[f0][3]*accK[f0][3]
                         + accQ[f1][2]*accK[f1][2] + accQ[f1][3]*accK[f1][3];
                p0 += __shfl_xor_sync(0xffffffffu, p0, 1);
                p0 += __shfl_xor_sync(0xffffffffu, p0, 2);
                p1 += __shfl_xor_sync(0xffffffffu, p1, 1);
                p1 += __shfl_xor_sync(0xffffffffu, p1, 2);
                if (qcol == 0) {
                    int h = half*4 + ((warp>>2)<<1) + hh;
                    int r0 = m_base + mf*16 + qrow;
                    if (r0 < nvalid) { int j = j0 + r0; g_dots[(size_t)h*SEQ*SEQ + (size_t)(j+d)*SEQ + j] = p0; }
                    int r1 = r0 + 8;
                    if (r1 < nvalid) { int j = j0 + r1; g_dots[(size_t)h*SEQ*SEQ + (size_t)(j+d)*SEQ + j] = p1; }
                }
            }
        }
    };

    const float* Pk_d = Pk + (size_t)d*HD*HD;
    const float* Pq_d = Pq + (size_t)(SEQ-1-d)*HD*HD;

    float accK[8][4], accQ[8][4];

    #pragma unroll
    for (int f=0;f<8;f++){accK[f][0]=0;accK[f][1]=0;accK[f][2]=0;accK[f][3]=0;}
    loadA(g_ak, j0);
    gemm_h(Pk_d, 0, accK);
    #pragma unroll
    for (int f=0;f<8;f++){accQ[f][0]=0;accQ[f][1]=0;accQ[f][2]=0;accQ[f][3]=0;}
    loadA(g_aq, j0 + d);
    gemm_h(Pq_d, 0, accQ);
    dots2_h(accQ, accK, 0);

    #pragma unroll
    for (int f=0;f<8;f++){accQ[f][0]=0;accQ[f][1]=0;accQ[f][2]=0;accQ[f][3]=0;}
    gemm_h(Pq_d, 64, accQ);
    #pragma unroll
    for (int f=0;f<8;f++){accK[f][0]=0;accK[f][1]=0;accK[f][2]=0;accK[f][3]=0;}
    loadA(g_ak, j0);
    gemm_h(Pk_d, 64, accK);
    dots2_h(accQ, accK, 1);

    {
        int nf0 = (warp>>2)*8;
        float acc[16][4];
        #pragma unroll
        for (int f=0;f<16;f++){acc[f][0]=0;acc[f][1]=0;acc[f][2]=0;acc[f][3]=0;}
        loadA(g_av, j0);
        const float* P = Pv + (size_t)d*HD*HD;
        int pr = tid>>5, pc4 = tid&31;
        const float* Pt = P + pr*HD + pc4*4;
        int khalf_f = (pr>>2)&1, kq_f = pr&3;
        int nf_f = pc4>>1;
        int qoff = (pc4&1)*4;
        auto stchunkV = [&](float* buf, float4 v, int q) {
            int rowbase_f = (q*2 + khalf_f)*32 + kq_f;
            buf[(rowbase_f + (qoff+0)*4)*20 + nf_f] = to_tf32(v.x);
            buf[(rowbase_f + (qoff+1)*4)*20 + nf_f] = to_tf32(v.y);
            buf[(rowbase_f + (qoff+2)*4)*20 + nf_f] = to_tf32(v.z);
            buf[(rowbase_f + (qoff+3)*4)*20 + nf_f] = to_tf32(v.w);
        };
        float4 pre[2];
        #pragma unroll
        for (int q=0;q<2;q++) pre[q] = *(const float4*)(Pt + q*8*HD);
        #pragma unroll
        for (int q=0;q<2;q++) stchunkV(sB, pre[q], q);
        #pragma unroll
        for (int q=0;q<2;q++) pre[q] = *(const float4*)(Pt + (16 + q*8)*HD);
        __syncthreads();
        int cur = 0;
        for (int kc=0; kc<128; kc+=16) {
            int nxt = cur^1;
            if (kc + 16 < 128) {
                #pragma unroll
                for (int q=0;q<2;q++) stchunkV(sB + nxt*PBUF_FLOATS, pre[q], q);
                if (kc + 32 < 128) {
                    #pragma unroll
                    for (int q=0;q<2;q++) pre[q] = *(const float4*)(Pt + (kc+32+q*8)*HD);
                }
            }
            if (act) {
                const float* buf = sB + cur*PBUF_FLOATS;
                #pragma unroll
                for (int ks=0; ks<2; ks++) {
                    int k0 = kc + ks*8;
                    unsigned a[2][4];
                    #pragma unroll
                    for (int mf=0; mf<2; mf++) {
                        int mr = m_base + mf*16 + qrow;
                        a[mf][0] = __float_as_uint(sA[mr  ][k0+qcol  ]);
                        a[mf][1] = __float_as_uint(sA[mr+8][k0+qcol  ]);
                        a[mf][2] = __float_as_uint(sA[mr  ][k0+qcol+4]);
                        a[mf][3] = __float_as_uint(sA[mr+8][k0+qcol+4]);
                    }
                    float4 b0p0 = *(const float4*)(buf + ((ks*2+0)*32 + lane)*20 + nf0);
                    float4 b0p1 = *(const float4*)(buf + ((ks*2+0)*32 + lane)*20 + nf0 + 4);
                    float4 b1p0 = *(const float4*)(buf + ((ks*2+1)*32 + lane)*20 + nf0);
                    float4 b1p1 = *(const float4*)(buf + ((ks*2+1)*32 + lane)*20 + nf0 + 4);
                    const float* b0a = (const float*)&b0p0;
                    const float* b0b = (const float*)&b0p1;
                    const float* b1a = (const float*)&b1p0;
                    const float* b1b = (const float*)&b1p1;
                    #pragma unroll
                    for (int nf=0; nf<8; nf++) {
                        unsigned b0 = __float_as_uint(nf < 4 ? b0a[nf] : b0b[nf-4]);
                        unsigned b1 = __float_as_uint(nf < 4 ? b1a[nf] : b1b[nf-4]);
                        mma_tf32(acc[nf],   a[0][0],a[0][1],a[0][2],a[0][3], b0,b1);
                        mma_tf32(acc[8+nf], a[1][0],a[1][1],a[1][2],a[1][3], b0,b1);
                    }
                }
            }
            __syncthreads();
            cur = nxt;
        }
        if (act) {
            int n_base = (warp>>2)*64;
            #pragma unroll
            for (int mf=0; mf<2; mf++) {
                #pragma unroll
                for (int nf=0; nf<8; nf++) {
                    int col = n_base + nf*8 + 2*qcol;
                    int r0 = m_base + mf*16 + qrow;
                    if (r0 < nvalid)
                        *(float2*)(g_uv + ((size_t)d*SEQ + j0 + r0)*HD + col) = make_float2(acc[mf*8+nf][0], acc[mf*8+nf][1]);
                    int r1 = r0 + 8;
                    if (r1 < nvalid)
                        *(float2*)(g_uv + ((size_t)d*SEQ + j0 + r1)*HD + col) = make_float2(acc[mf*8+nf][2], acc[mf*8+nf][3]);
                }
            }
        }
    }
}

// ---------------- dots1 + combine + causal softmax ----------------
__global__ void __launch_bounds__(256) attn_kernel() {
    int h  = blockIdx.y;
    int i0 = blockIdx.x * 16;
    __shared__ float sQ[16][68];
    __shared__ float sK[32][68];
    __shared__ float sD[16][512];
    int tid = threadIdx.x;
    {   int r = tid>>4, c4 = tid&15;
        *(float4*)&sQ[r][c4*4] = *(const float4*)(g_qkv + (i0+r)*1536 + h*64 + c4*4); }
    int r2 = tid>>4, jj = tid&15;
    for (int jc = 0; jc < 512; jc += 32) {
        __syncthreads();
        #pragma unroll
        for (int q=0; q<2; q++) {
            int idx = q*256 + tid; int r = idx>>4, c4 = idx&15;
            *(float4*)&sK[r][c4*4] = *(const float4*)(g_qkv + (jc+r)*1536 + 512 + h*64 + c4*4);
        }
        __syncthreads();
        float a0 = 0.f, a1 = 0.f;
        #pragma unroll
        for (int c4 = 0; c4 < 16; c4++) {
            float4 qv = *(const float4*)&sQ[r2][c4*4];
            float4 k0 = *(const float4*)&sK[jj][c4*4];
            float4 k1 = *(const float4*)&sK[jj+16][c4*4];
            a0 += qv.x*k0.x + qv.y*k0.y + qv.z*k0.z + qv.w*k0.w;
            a1 += qv.x*k1.x + qv.y*k1.y + qv.z*k1.z + qv.w*k1.w;
        }
        sD[r2][jc+jj]    = a0;
        sD[r2][jc+jj+16] = a1;
    }
    __syncthreads();
    int w = tid>>5, lane = tid&31;
    for (int rr = 2*w; rr < 2*w+2; rr++) {
        int i = i0 + rr;
        float vals[16];
        float m = -1e30f;
        #pragma unroll
        for (int t=0; t<16; t++) {
            int j = lane + t*32;
            float dv = -1e30f;
            if (j <= i)
                dv = 0.0625f * (sD[rr][j] + g_dots[(size_t)h*SEQ*SEQ + (size_t)i*SEQ + j]);
            vals[t] = dv;
            m = fmaxf(m, dv);
        }
        #pragma unroll
        for (int o=16;o;o>>=1) m = fmaxf(m, __shfl_xor_sync(0xffffffffu, m, o));
        float s = 0.f;
        #pragma unroll
        for (int t=0; t<16; t++) {
            float e = (vals[t] > -1e29f) ? __expf(vals[t]-m) : 0.f;
            vals[t] = e; s += e;
        }
        #pragma unroll
        for (int o=16;o;o>>=1) s += __shfl_xor_sync(0xffffffffu, s, o);
        float inv = 1.f / s;
        #pragma unroll
        for (int t=0; t<16; t++) {
            int j = lane + t*32;
            g_dots[(size_t)h*SEQ*SEQ + (size_t)i*SEQ + j] = vals[t]*inv;
        }
    }
}

// ---------------- out1 = attn @ v1 ----------------
__global__ void __launch_bounds__(256) out1_kernel() {
    int h = blockIdx.y, i0 = blockIdx.x*32;
    __shared__ float sAt[32][36];
    __shared__ float sV[32][68];
    int tid = threadIdx.x, ty = tid>>4, tx = tid&15;
    float acc[2][4] = {};
    for (int jc = 0; jc < 512; jc += 32) {
        __syncthreads();
        {   int r = tid>>3, c4 = tid&7;
            *(float4*)&sAt[r][c4*4] = *(const float4*)(g_dots + (size_t)h*SEQ*SEQ + (size_t)(i0+r)*512 + jc + c4*4); }
        #pragma unroll
        for (int q=0; q<2; q++) {
            int idx = q*256 + tid; int r = idx>>4, c4 = idx&15;
            *(float4*)&sV[r][c4*4] = *(const float4*)(g_qkv + (jc+r)*1536 + 1024 + h*64 + c4*4);
        }
        __syncthreads();
        #pragma unroll
        for (int k=0; k<32; k++) {
            float a0 = sAt[ty][k], a1 = sAt[ty+16][k];
            float4 v4 = *(float4*)&sV[k][tx*4];
            acc[0][0]+=a0*v4.x; acc[0][1]+=a0*v4.y; acc[0][2]+=a0*v4.z; acc[0][3]+=a0*v4.w;
            acc[1][0]+=a1*v4.x; acc[1][1]+=a1*v4.y; acc[1][2]+=a1*v4.z; acc[1][3]+=a1*v4.w;
        }
    }
    *(float4*)(g_out1 + (i0+ty)*512    + h*64 + tx*4) = make_float4(acc[0][0],acc[0][1],acc[0][2],acc[0][3]);
    *(float4*)(g_out1 + (i0+ty+16)*512 + h*64 + tx*4) = make_float4(acc[1][0],acc[1][1],acc[1][2],acc[1][3]);
}

// ---------------- out2[i,c] = sum_{j<=i} attn[h(c),i,j] * Uv[i-j][j][c] ----------------
// 1024 threads: c = tid&127, 8-way j-split (part = tid>>7), smem tree reduce.
__global__ void __launch_bounds__(1024) out2_kernel() {
    int i = blockIdx.x;
    int tid = threadIdx.x;
    int c = tid & 127;
    int part = tid >> 7;
    int h = c >> 4;
    const float* arow = g_dots + (size_t)h*SEQ*SEQ + (size_t)i*SEQ;
    int len = i + 1;
    int chunk = (len + 7) >> 3;
    int jb = part*chunk, je = min(len, jb + chunk);
    float a0=0.f, a1=0.f, a2=0.f, a3=0.f;
    int j = jb;
    for (; j+4 <= je; j += 4) {
        a0 += arow[j]   * g_uv[((size_t)(i-j  )*SEQ + j  )*HD + c];
        a1 += arow[j+1] * g_uv[((size_t)(i-j-1)*SEQ + j+1)*HD + c];
        a2 += arow[j+2] * g_uv[((size_t)(i-j-2)*SEQ + j+2)*HD + c];
        a3 += arow[j+3] * g_uv[((size_t)(i-j-3)*SEQ + j+3)*HD + c];
    }
    for (; j < je; j++)
        a0 += arow[j] * g_uv[((size_t)(i-j)*SEQ + j)*HD + c];
    __shared__ float red[1024];
    red[tid] = (a0+a1) + (a2+a3);
    __syncthreads();
    if (part < 4) red[tid] += red[tid + 512];
    __syncthreads();
    if (part < 2) red[tid] += red[tid + 256];
    __syncthreads();
    if (part == 0)
        g_out2[i*HD + c] = red[c] + red[c + 128];
}

// ---------------- launch ----------------
extern "C" void kernel_launch(void* const* d_in, const int* in_sizes, int n_in,
                              void* d_out, int out_size) {
    const float* x     = (const float*)d_in[0];
    const float* ln_w  = (const float*)d_in[1];
    const float* ln_b  = (const float*)d_in[2];
    const float* w_qkv = (const float*)d_in[3];
    const float* w_q1  = (const float*)d_in[4];
    const float* p_q2  = (const float*)d_in[5];
    const float* w_k1  = (const float*)d_in[6];
    const float* p_k2  = (const float*)d_in[7];
    const float* w_v1  = (const float*)d_in[8];
    const float* p_v2  = (const float*)d_in[9];
    const float* w_v3  = (const float*)d_in[10];
    const float* w_out = (const float*)d_in[11];
    const float* b_out = (const float*)d_in[12];
    float* out = (float*)d_out;

    float *p_xn, *p_qkvb, *p_aq, *p_ak, *p_av, *p_out1b, *p_out2b, *p_tmpb;
    cudaGetSymbolAddress((void**)&p_xn,   g_xn);
    cudaGetSymbolAddress((void**)&p_qkvb, g_qkv);
    cudaGetSymbolAddress((void**)&p_aq,   g_aq);
    cudaGetSymbolAddress((void**)&p_ak,   g_ak);
    cudaGetSymbolAddress((void**)&p_av,   g_av);
    cudaGetSymbolAddress((void**)&p_out1b,g_out1);
    cudaGetSymbolAddress((void**)&p_out2b,g_out2);
    cudaGetSymbolAddress((void**)&p_tmpb, g_tmp);

    // opt-in >48KB dynamic smem for diag_mma (idempotent; not a stream op)
    cudaFuncSetAttribute(diag_mma, cudaFuncAttributeMaxDynamicSharedMemorySize, DIAG_SMEM);

    ln_kernel<<<512, 256>>>(x, ln_w, ln_b);

    // qkv = xn @ w_qkv  (512x1536x512)
    mma_gemm<0><<<dim3(24,8), 256>>>(p_xn, w_qkv, p_qkvb, 1536, 512, nullptr);
    // aq/ak/av = xn @ {w_q1,w_k1,w_v1}  (512x128x512, fused)
    mma_gemm3<<<dim3(2,8,3), 256>>>(p_xn, w_q1, w_k1, w_v1, p_aq, p_ak, p_av, 128, 512);

    diag_mma<<<dim3(4,512), 256, DIAG_SMEM>>>(p_q2, p_k2, p_v2);

    attn_kernel<<<dim3(32,8), 256>>>();
    out1_kernel<<<dim3(16,8), 256>>>();
    out2_kernel<<<512, 1024>>>();

    // tmp = (out1 + out2 @ w_v3) * 0.5   (512x512x128)
    mma_gemm<1><<<dim3(8,8), 256>>>(p_out2b, w_v3, p_tmpb, 512, 128, p_out1b);
    // out = tmp @ w_out + b_out          (512x512x512)
    mma_gemm<2><<<dim3(8,8), 256>>>(p_tmpb, w_out, out, 512, 512, b_out);
}